// round 11
// baseline (speedup 1.0000x reference)
#include <cuda_runtime.h>
#include <cstdint>
#include <cstddef>

// ---------------- problem constants ----------------
#define B_      8
#define S_      4094
#define NH_     8
#define HD_     64
#define TQ      128        // queries per CTA (M)
#define NKEY    256        // padded key rows per CTA (254 real + 2 always-masked)
#define NCHUNK  32         // ceil(4094/128)
#define QPW     16         // query rows per warp

// ---------------- packed smem layout ----------------
// All tiles store float2 PAIRS {x[k], x[k+4]} so each MMA fragment operand is
// one LDS.64. Strides chosen for conflict-free 64-bit half-warp transactions.
#define QP2 36             // pQ row stride in float2 (72 floats): banks 8*lr+2*lc
#define KP2 36             // pK row stride in float2
#define VP2 68             // pV row stride in float2 (136 floats): banks 8*lc+2*lr
#define OSTR 68            // staging for cross-half O reduction [16][68] per pair

#define OFF_Q  0                               // 128*72      = 9216
#define OFF_K  (TQ * QP2 * 2)                  // 9216; 256*72 = 18432
#define OFF_V  (OFF_K + NKEY * KP2 * 2)        // 27648; 128*136 = 17408
#define OFF_O  (OFF_V + (NKEY / 2) * VP2 * 2)  // 45056
#define OPW    (QPW * OSTR)                    // 1088 floats per pair
#define OFF_PS (OFF_O + 8 * OPW)               // 53760
#define SMEM_FLOATS (OFF_PS + 8 * QPW)         // 53888 floats = 215552 B

// ---------------- helpers ----------------
__device__ __forceinline__ float to_tf32(float x) {
    uint32_t u;
    asm("cvt.rna.tf32.f32 %0, %1;" : "=r"(u) : "f"(x));
    return __uint_as_float(u);
}
__device__ __forceinline__ uint32_t fb(float x) { return __float_as_uint(x); }

// m16n8k8 tf32 mma, fp32 accumulate (family-portable, sm_80+)
__device__ __forceinline__ void mma8(float* d, const uint32_t* a, const uint32_t* b) {
    asm volatile(
        "mma.sync.aligned.m16n8k8.row.col.f32.tf32.tf32.f32 "
        "{%0,%1,%2,%3}, {%4,%5,%6,%7}, {%8,%9}, {%0,%1,%2,%3};"
        : "+f"(d[0]), "+f"(d[1]), "+f"(d[2]), "+f"(d[3])
        : "r"(a[0]), "r"(a[1]), "r"(a[2]), "r"(a[3]), "r"(b[0]), "r"(b[1]));
}

// ---------------- kernel ----------------
__global__ __launch_bounds__(512, 1)
void window_attn_mma(const float* __restrict__ qg, const float* __restrict__ kg,
                     const float* __restrict__ vg, float* __restrict__ og)
{
    extern __shared__ float sm[];
    float2* pQ = reinterpret_cast<float2*>(sm + OFF_Q);
    float2* pK = reinterpret_cast<float2*>(sm + OFF_K);
    float2* pV = reinterpret_cast<float2*>(sm + OFF_V);
    float*  sPS = sm + OFF_PS;

    const int bx    = blockIdx.x;
    const int chunk = bx & (NCHUNK - 1);
    const int head  = (bx >> 5) & (NH_ - 1);
    const int batch = bx >> 8;
    const int t0    = chunk * TQ;

    const int tid  = threadIdx.x;
    const int w    = tid >> 5;
    const int lane = tid & 31;
    const int lr   = lane >> 2;   // row-in-fragment
    const int lc   = lane & 3;    // col-in-fragment
    const int wq   = w & 7;       // query group (16 rows)
    const int kh   = w >> 3;      // key half (128 keys)

    // ---- fill packed Q: pQ[m][4g+j] = {Q[m][8g+j], Q[m][8g+j+4]}, scaled 1/8
    for (int idx = tid; idx < TQ * 8; idx += 512) {
        int m = idx >> 3, g = idx & 7;
        int t = t0 + m;
        float4 a = make_float4(0.f, 0.f, 0.f, 0.f), b = a;
        if (t < S_) {
            const float4* src = reinterpret_cast<const float4*>(
                qg + (((size_t)batch * S_ + t) * NH_ + head) * HD_ + 8 * g);
            a = src[0]; b = src[1];
            a.x = to_tf32(a.x * 0.125f); a.y = to_tf32(a.y * 0.125f);
            a.z = to_tf32(a.z * 0.125f); a.w = to_tf32(a.w * 0.125f);
            b.x = to_tf32(b.x * 0.125f); b.y = to_tf32(b.y * 0.125f);
            b.z = to_tf32(b.z * 0.125f); b.w = to_tf32(b.w * 0.125f);
        }
        float* dst = sm + OFF_Q + m * (QP2 * 2) + 8 * g;
        reinterpret_cast<float4*>(dst)[0] = make_float4(a.x, b.x, a.y, b.y);
        reinterpret_cast<float4*>(dst)[1] = make_float4(a.z, b.z, a.w, b.w);
    }
    // ---- fill packed K; out-of-sequence rows ZERO (reference's zero padding)
    for (int idx = tid; idx < NKEY * 8; idx += 512) {
        int r = idx >> 3, g = idx & 7;
        int gl = t0 - 63 + r;
        float4 a = make_float4(0.f, 0.f, 0.f, 0.f), b = a;
        if (gl >= 0 && gl < S_) {
            const float4* src = reinterpret_cast<const float4*>(
                kg + (((size_t)batch * S_ + gl) * NH_ + head) * HD_ + 8 * g);
            a = src[0]; b = src[1];
            a.x = to_tf32(a.x); a.y = to_tf32(a.y); a.z = to_tf32(a.z); a.w = to_tf32(a.w);
            b.x = to_tf32(b.x); b.y = to_tf32(b.y); b.z = to_tf32(b.z); b.w = to_tf32(b.w);
        }
        float* dst = sm + OFF_K + r * (KP2 * 2) + 8 * g;
        reinterpret_cast<float4*>(dst)[0] = make_float4(a.x, b.x, a.y, b.y);
        reinterpret_cast<float4*>(dst)[1] = make_float4(a.z, b.z, a.w, b.w);
    }
    // ---- fill packed V: pV[p][d] = {V[key][d], V[key+4][d]},
    //      key = 8*(p>>2)+(p&3). Out-of-sequence rows ZERO.
    for (int idx = tid; idx < (NKEY / 2) * 16; idx += 512) {
        int p = idx >> 4, dg = idx & 15;
        int k1 = 8 * (p >> 2) + (p & 3);
        int g1 = t0 - 63 + k1, g2 = g1 + 4;
        float4 a = make_float4(0.f, 0.f, 0.f, 0.f), b = a;
        if (g1 >= 0 && g1 < S_) {
            a = reinterpret_cast<const float4*>(
                vg + (((size_t)batch * S_ + g1) * NH_ + head) * HD_ + 4 * dg)[0];
            a.x = to_tf32(a.x); a.y = to_tf32(a.y); a.z = to_tf32(a.z); a.w = to_tf32(a.w);
        }
        if (g2 >= 0 && g2 < S_) {
            b = reinterpret_cast<const float4*>(
                vg + (((size_t)batch * S_ + g2) * NH_ + head) * HD_ + 4 * dg)[0];
            b.x = to_tf32(b.x); b.y = to_tf32(b.y); b.z = to_tf32(b.z); b.w = to_tf32(b.w);
        }
        float* dst = sm + OFF_V + p * (VP2 * 2) + 8 * dg;
        reinterpret_cast<float4*>(dst)[0] = make_float4(a.x, b.x, a.y, b.y);
        reinterpret_cast<float4*>(dst)[1] = make_float4(a.z, b.z, a.w, b.w);
    }
    __syncthreads();

    const int qbase = wq * QPW;                // this warp's first query row
    const int srcA  = (lr << 2) + (lc >> 1);   // shuffle sources for P permute
    const int srcB  = srcA + 2;
    const bool odd  = lc & 1;

    float Oacc[8][4];
    #pragma unroll
    for (int nt = 0; nt < 8; ++nt)
        #pragma unroll
        for (int e = 0; e < 4; ++e) Oacc[nt][e] = 0.f;
    float psum[2] = {0.f, 0.f};

    #pragma unroll
    for (int c = 0; c < 2; ++c) {
        const int kc0 = kh * 128 + c * 64;     // this warp's key chunk

        // ---- GEMM1 chunk: S[16 x 64] = Q_warp @ K_chunk^T
        float Sacc[8][4];
        #pragma unroll
        for (int nt = 0; nt < 8; ++nt)
            #pragma unroll
            for (int e = 0; e < 4; ++e) Sacc[nt][e] = 0.f;

        #pragma unroll
        for (int kk = 0; kk < 8; ++kk) {
            uint32_t afr[4];
            {
                const float2* qp = pQ + (qbase + lr) * QP2 + kk * 4 + lc;
                float2 fa = qp[0];            // {Q[m][k],   Q[m][k+4]}
                float2 fc = qp[8 * QP2];      // {Q[m+8][k], Q[m+8][k+4]}
                afr[0] = fb(fa.x); afr[1] = fb(fc.x);
                afr[2] = fb(fa.y); afr[3] = fb(fc.y);
            }
            #pragma unroll
            for (int nt = 0; nt < 8; ++nt) {
                float2 bv = pK[(kc0 + nt * 8 + lr) * KP2 + kk * 4 + lc];
                uint32_t bfr[2] = { fb(bv.x), fb(bv.y) };
                mma8(Sacc[nt], afr, bfr);
            }
        }

        // ---- band mask + exp (tf32-rounded) + row-sum partials, in registers
        #pragma unroll
        for (int h = 0; h < 2; ++h) {
            const int m = qbase + lr + 8 * h;            // local query idx
            #pragma unroll
            for (int nt = 0; nt < 8; ++nt) {
                const int j0 = kc0 + nt * 8 + 2 * lc;    // key window idx
                float s0 = Sacc[nt][2 * h + 0];
                float s1 = Sacc[nt][2 * h + 1];
                float p0 = (j0     >= m && j0     <= m + 126) ? __expf(s0) : 0.f;
                float p1 = (j0 + 1 >= m && j0 + 1 <= m + 126) ? __expf(s1) : 0.f;
                psum[h] += p0 + p1;
                Sacc[nt][2 * h + 0] = to_tf32(p0);
                Sacc[nt][2 * h + 1] = to_tf32(p1);
            }
        }

        // ---- GEMM2 partial: O[16 x 64] += P_chunk @ V_chunk.
        // A-fragment from D-fragment P via intra-warp shuffles.
        #pragma unroll
        for (int kk = 0; kk < 8; ++kk) {
            float q0 = __shfl_sync(0xffffffffu, Sacc[kk][0], srcA);
            float q1 = __shfl_sync(0xffffffffu, Sacc[kk][1], srcA);
            float q2 = __shfl_sync(0xffffffffu, Sacc[kk][2], srcA);
            float q3 = __shfl_sync(0xffffffffu, Sacc[kk][3], srcA);
            float r0 = __shfl_sync(0xffffffffu, Sacc[kk][0], srcB);
            float r1 = __shfl_sync(0xffffffffu, Sacc[kk][1], srcB);
            float r2 = __shfl_sync(0xffffffffu, Sacc[kk][2], srcB);
            float r3 = __shfl_sync(0xffffffffu, Sacc[kk][3], srcB);
            uint32_t afr[4];
            afr[0] = fb(odd ? q1 : q0);
            afr[1] = fb(odd ? q3 : q2);
            afr[2] = fb(odd ? r1 : r0);
            afr[3] = fb(odd ? r3 : r2);
            const int prow = (kc0 >> 1) + kk * 4 + lc;   // packed V pair-row
            #pragma unroll
            for (int nt = 0; nt < 8; ++nt) {
                float2 bv = pV[prow * VP2 + nt * 8 + lr];
                uint32_t bfr[2] = { fb(bv.x), fb(bv.y) };
                mma8(Oacc[nt], afr, bfr);
            }
        }
    }

    // ---- row-sum partials: reduce across the 4 lanes of each quad
    #pragma unroll
    for (int h = 0; h < 2; ++h) {
        float s = psum[h];
        s += __shfl_xor_sync(0xffffffffu, s, 1);
        s += __shfl_xor_sync(0xffffffffu, s, 2);
        psum[h] = s;
    }

    // ---- cross-half combine: key-half-1 warps stage raw O + psum in smem
    // (staging region has no prior readers/writers -> no sync needed before)
    if (kh == 1) {
        float* so = sm + OFF_O + wq * OPW;
        #pragma unroll
        for (int h = 0; h < 2; ++h) {
            #pragma unroll
            for (int nt = 0; nt < 8; ++nt) {
                float2 o;
                o.x = Oacc[nt][2 * h + 0];
                o.y = Oacc[nt][2 * h + 1];
                *reinterpret_cast<float2*>(so + (lr + 8 * h) * OSTR + nt * 8 + 2 * lc) = o;
            }
            if (lc == 0) sPS[wq * QPW + lr + 8 * h] = psum[h];
        }
    }
    __syncthreads();

    // ---- key-half-0 warps add the staged half, normalize, store
    if (kh == 0) {
        const float* so = sm + OFF_O + wq * OPW;
        #pragma unroll
        for (int h = 0; h < 2; ++h) {
            const int m = qbase + lr + 8 * h;
            const int t = t0 + m;
            if (t < S_) {
                const float inv = 1.0f / (psum[h] + sPS[wq * QPW + lr + 8 * h]);
                float* dst = og + (((size_t)batch * S_ + t) * NH_ + head) * HD_;
                #pragma unroll
                for (int nt = 0; nt < 8; ++nt) {
                    float2 s2 = *reinterpret_cast<const float2*>(
                        so + (lr + 8 * h) * OSTR + nt * 8 + 2 * lc);
                    float2 o;
                    o.x = (Oacc[nt][2 * h + 0] + s2.x) * inv;
                    o.y = (Oacc[nt][2 * h + 1] + s2.y) * inv;
                    *reinterpret_cast<float2*>(dst + nt * 8 + 2 * lc) = o;
                }
            }
        }
    }
}

extern "C" void kernel_launch(void* const* d_in, const int* in_sizes, int n_in,
                              void* d_out, int out_size)
{
    const float* q = (const float*)d_in[0];
    const float* k = (const float*)d_in[1];
    const float* v = (const float*)d_in[2];
    float* o = (float*)d_out;

    (void)cudaFuncSetAttribute(window_attn_mma,
                               cudaFuncAttributeMaxDynamicSharedMemorySize,
                               SMEM_FLOATS * (int)sizeof(float));

    window_attn_mma<<<B_ * NH_ * NCHUNK, 512, SMEM_FLOATS * (int)sizeof(float)>>>(q, k, v, o);
}

// round 12
// speedup vs baseline: 1.2324x; 1.2324x over previous
#include <cuda_runtime.h>
#include <cstdint>
#include <cstddef>

// ---------------- problem constants ----------------
#define B_      8
#define S_      4094
#define NH_     8
#define HD_     64
#define TQ      128        // queries per CTA (M)
#define NKEY    256        // padded key rows per CTA (254 real + 2 always-masked)
#define NCHUNK  32         // ceil(4094/128)
#define QPW     16         // query rows per warp
#define KPW     72         // keys per warp (band-aware: 2 warps cover the 144-key band)
#define NT1     9          // n-tiles of 8 keys per warp

// ---------------- packed smem layout ----------------
// All tiles store float2 PAIRS {x[k], x[k+4]} so each MMA fragment operand is
// one LDS.64. Strides chosen for conflict-free 64-bit half-warp transactions.
#define QP2 36             // pQ row stride in float2 (72 floats)
#define KP2 36             // pK row stride in float2
#define VP2 68             // pV row stride in float2 (136 floats)
#define OSTR 68            // staging for cross-half O reduction [16][68] per pair

#define OFF_Q  0                               // 128*72      = 9216
#define OFF_K  (TQ * QP2 * 2)                  // 9216; 256*72 = 18432
#define OFF_V  (OFF_K + NKEY * KP2 * 2)        // 27648; 128*136 = 17408
#define OFF_O  (OFF_V + (NKEY / 2) * VP2 * 2)  // 45056
#define OPW    (QPW * OSTR)                    // 1088 floats per pair
#define OFF_PS (OFF_O + 8 * OPW)               // 53760
#define SMEM_FLOATS (OFF_PS + 8 * QPW)         // 53888 floats = 215552 B

// ---------------- helpers ----------------
__device__ __forceinline__ float to_tf32(float x) {
    uint32_t u;
    asm("cvt.rna.tf32.f32 %0, %1;" : "=r"(u) : "f"(x));
    return __uint_as_float(u);
}
__device__ __forceinline__ uint32_t fb(float x) { return __float_as_uint(x); }

// m16n8k8 tf32 mma, fp32 accumulate (family-portable, sm_80+)
__device__ __forceinline__ void mma8(float* d, const uint32_t* a, const uint32_t* b) {
    asm volatile(
        "mma.sync.aligned.m16n8k8.row.col.f32.tf32.tf32.f32 "
        "{%0,%1,%2,%3}, {%4,%5,%6,%7}, {%8,%9}, {%0,%1,%2,%3};"
        : "+f"(d[0]), "+f"(d[1]), "+f"(d[2]), "+f"(d[3])
        : "r"(a[0]), "r"(a[1]), "r"(a[2]), "r"(a[3]), "r"(b[0]), "r"(b[1]));
}

// ---------------- kernel ----------------
__global__ __launch_bounds__(512, 1)
void window_attn_mma(const float* __restrict__ qg, const float* __restrict__ kg,
                     const float* __restrict__ vg, float* __restrict__ og)
{
    extern __shared__ float sm[];
    float2* pQ = reinterpret_cast<float2*>(sm + OFF_Q);
    float2* pK = reinterpret_cast<float2*>(sm + OFF_K);
    float2* pV = reinterpret_cast<float2*>(sm + OFF_V);
    float*  sPS = sm + OFF_PS;

    const int bx    = blockIdx.x;
    const int chunk = bx & (NCHUNK - 1);
    const int head  = (bx >> 5) & (NH_ - 1);
    const int batch = bx >> 8;
    const int t0    = chunk * TQ;

    const int tid  = threadIdx.x;
    const int w    = tid >> 5;
    const int lane = tid & 31;
    const int lr   = lane >> 2;   // row-in-fragment
    const int lc   = lane & 3;    // col-in-fragment
    const int wq   = w & 7;       // query group (16 rows)
    const int kh   = w >> 3;      // key half of the band (72 keys each)

    // ---- fill packed Q: pQ[m][4g+j] = {Q[m][8g+j], Q[m][8g+j+4]}, scaled 1/8
    for (int idx = tid; idx < TQ * 8; idx += 512) {
        int m = idx >> 3, g = idx & 7;
        int t = t0 + m;
        float4 a = make_float4(0.f, 0.f, 0.f, 0.f), b = a;
        if (t < S_) {
            const float4* src = reinterpret_cast<const float4*>(
                qg + (((size_t)batch * S_ + t) * NH_ + head) * HD_ + 8 * g);
            a = src[0]; b = src[1];
            a.x = to_tf32(a.x * 0.125f); a.y = to_tf32(a.y * 0.125f);
            a.z = to_tf32(a.z * 0.125f); a.w = to_tf32(a.w * 0.125f);
            b.x = to_tf32(b.x * 0.125f); b.y = to_tf32(b.y * 0.125f);
            b.z = to_tf32(b.z * 0.125f); b.w = to_tf32(b.w * 0.125f);
        }
        float* dst = sm + OFF_Q + m * (QP2 * 2) + 8 * g;
        reinterpret_cast<float4*>(dst)[0] = make_float4(a.x, b.x, a.y, b.y);
        reinterpret_cast<float4*>(dst)[1] = make_float4(a.z, b.z, a.w, b.w);
    }
    // ---- fill packed K; out-of-sequence rows ZERO (reference's zero padding)
    for (int idx = tid; idx < NKEY * 8; idx += 512) {
        int r = idx >> 3, g = idx & 7;
        int gl = t0 - 63 + r;
        float4 a = make_float4(0.f, 0.f, 0.f, 0.f), b = a;
        if (gl >= 0 && gl < S_) {
            const float4* src = reinterpret_cast<const float4*>(
                kg + (((size_t)batch * S_ + gl) * NH_ + head) * HD_ + 8 * g);
            a = src[0]; b = src[1];
            a.x = to_tf32(a.x); a.y = to_tf32(a.y); a.z = to_tf32(a.z); a.w = to_tf32(a.w);
            b.x = to_tf32(b.x); b.y = to_tf32(b.y); b.z = to_tf32(b.z); b.w = to_tf32(b.w);
        }
        float* dst = sm + OFF_K + r * (KP2 * 2) + 8 * g;
        reinterpret_cast<float4*>(dst)[0] = make_float4(a.x, b.x, a.y, b.y);
        reinterpret_cast<float4*>(dst)[1] = make_float4(a.z, b.z, a.w, b.w);
    }
    // ---- fill packed V: pV[p][d] = {V[key][d], V[key+4][d]},
    //      key = 8*(p>>2)+(p&3). Out-of-sequence rows ZERO.
    for (int idx = tid; idx < (NKEY / 2) * 16; idx += 512) {
        int p = idx >> 4, dg = idx & 15;
        int k1 = 8 * (p >> 2) + (p & 3);
        int g1 = t0 - 63 + k1, g2 = g1 + 4;
        float4 a = make_float4(0.f, 0.f, 0.f, 0.f), b = a;
        if (g1 >= 0 && g1 < S_) {
            a = reinterpret_cast<const float4*>(
                vg + (((size_t)batch * S_ + g1) * NH_ + head) * HD_ + 4 * dg)[0];
            a.x = to_tf32(a.x); a.y = to_tf32(a.y); a.z = to_tf32(a.z); a.w = to_tf32(a.w);
        }
        if (g2 >= 0 && g2 < S_) {
            b = reinterpret_cast<const float4*>(
                vg + (((size_t)batch * S_ + g2) * NH_ + head) * HD_ + 4 * dg)[0];
            b.x = to_tf32(b.x); b.y = to_tf32(b.y); b.z = to_tf32(b.z); b.w = to_tf32(b.w);
        }
        float* dst = sm + OFF_V + p * (VP2 * 2) + 8 * dg;
        reinterpret_cast<float4*>(dst)[0] = make_float4(a.x, b.x, a.y, b.y);
        reinterpret_cast<float4*>(dst)[1] = make_float4(a.z, b.z, a.w, b.w);
    }
    __syncthreads();

    const int qbase = wq * QPW;                // this warp's first query row
    const int kbase = qbase + kh * KPW;        // this warp's first key row:
                                               //   band [qbase, qbase+144) split in two;
                                               //   every key with a nonzero mask term
                                               //   for these queries is covered exactly once
    const int srcA  = (lr << 2) + (lc >> 1);   // shuffle sources for P permute
    const int srcB  = srcA + 2;
    const bool odd  = lc & 1;

    float Oacc[8][4];
    #pragma unroll
    for (int nt = 0; nt < 8; ++nt)
        #pragma unroll
        for (int e = 0; e < 4; ++e) Oacc[nt][e] = 0.f;
    float psum[2] = {0.f, 0.f};

    // ---- GEMM1: S[16 x 72] = Q_warp @ K_band^T (9 n-tiles of 8 keys)
    float Sacc[NT1][4];
    #pragma unroll
    for (int nt = 0; nt < NT1; ++nt)
        #pragma unroll
        for (int e = 0; e < 4; ++e) Sacc[nt][e] = 0.f;

    #pragma unroll
    for (int kk = 0; kk < 8; ++kk) {
        uint32_t afr[4];
        {
            const float2* qp = pQ + (qbase + lr) * QP2 + kk * 4 + lc;
            float2 fa = qp[0];            // {Q[m][k],   Q[m][k+4]}
            float2 fc = qp[8 * QP2];      // {Q[m+8][k], Q[m+8][k+4]}
            afr[0] = fb(fa.x); afr[1] = fb(fc.x);
            afr[2] = fb(fa.y); afr[3] = fb(fc.y);
        }
        #pragma unroll
        for (int nt = 0; nt < NT1; ++nt) {
            float2 bv = pK[(kbase + nt * 8 + lr) * KP2 + kk * 4 + lc];
            uint32_t bfr[2] = { fb(bv.x), fb(bv.y) };
            mma8(Sacc[nt], afr, bfr);
        }
    }

    // ---- band mask + exp (tf32-rounded) + row-sum partials, in registers
    #pragma unroll
    for (int h = 0; h < 2; ++h) {
        const int m = qbase + lr + 8 * h;            // local query idx
        #pragma unroll
        for (int nt = 0; nt < NT1; ++nt) {
            const int j0 = kbase + nt * 8 + 2 * lc;  // key window idx
            float s0 = Sacc[nt][2 * h + 0];
            float s1 = Sacc[nt][2 * h + 1];
            float p0 = (j0     >= m && j0     <= m + 126) ? __expf(s0) : 0.f;
            float p1 = (j0 + 1 >= m && j0 + 1 <= m + 126) ? __expf(s1) : 0.f;
            psum[h] += p0 + p1;
            Sacc[nt][2 * h + 0] = to_tf32(p0);
            Sacc[nt][2 * h + 1] = to_tf32(p1);
        }
    }

    // ---- GEMM2: O[16 x 64] += P_band @ V_band (K = 72 keys, 9 k-groups).
    // A-fragment from D-fragment P via intra-warp shuffles.
    #pragma unroll
    for (int kk = 0; kk < NT1; ++kk) {
        float q0 = __shfl_sync(0xffffffffu, Sacc[kk][0], srcA);
        float q1 = __shfl_sync(0xffffffffu, Sacc[kk][1], srcA);
        float q2 = __shfl_sync(0xffffffffu, Sacc[kk][2], srcA);
        float q3 = __shfl_sync(0xffffffffu, Sacc[kk][3], srcA);
        float r0 = __shfl_sync(0xffffffffu, Sacc[kk][0], srcB);
        float r1 = __shfl_sync(0xffffffffu, Sacc[kk][1], srcB);
        float r2 = __shfl_sync(0xffffffffu, Sacc[kk][2], srcB);
        float r3 = __shfl_sync(0xffffffffu, Sacc[kk][3], srcB);
        uint32_t afr[4];
        afr[0] = fb(odd ? q1 : q0);
        afr[1] = fb(odd ? q3 : q2);
        afr[2] = fb(odd ? r1 : r0);
        afr[3] = fb(odd ? r3 : r2);
        const int prow = (kbase >> 1) + kk * 4 + lc;   // packed V pair-row
        #pragma unroll
        for (int nt = 0; nt < 8; ++nt) {
            float2 bv = pV[prow * VP2 + nt * 8 + lr];
            uint32_t bfr[2] = { fb(bv.x), fb(bv.y) };
            mma8(Oacc[nt], afr, bfr);
        }
    }

    // ---- row-sum partials: reduce across the 4 lanes of each quad
    #pragma unroll
    for (int h = 0; h < 2; ++h) {
        float s = psum[h];
        s += __shfl_xor_sync(0xffffffffu, s, 1);
        s += __shfl_xor_sync(0xffffffffu, s, 2);
        psum[h] = s;
    }

    // ---- cross-half combine: key-half-1 warps stage raw O + psum in smem
    // (staging region has no prior readers/writers -> no sync needed before)
    if (kh == 1) {
        float* so = sm + OFF_O + wq * OPW;
        #pragma unroll
        for (int h = 0; h < 2; ++h) {
            #pragma unroll
            for (int nt = 0; nt < 8; ++nt) {
                float2 o;
                o.x = Oacc[nt][2 * h + 0];
                o.y = Oacc[nt][2 * h + 1];
                *reinterpret_cast<float2*>(so + (lr + 8 * h) * OSTR + nt * 8 + 2 * lc) = o;
            }
            if (lc == 0) sPS[wq * QPW + lr + 8 * h] = psum[h];
        }
    }
    __syncthreads();

    // ---- key-half-0 warps add the staged half, normalize, store
    if (kh == 0) {
        const float* so = sm + OFF_O + wq * OPW;
        #pragma unroll
        for (int h = 0; h < 2; ++h) {
            const int m = qbase + lr + 8 * h;
            const int t = t0 + m;
            if (t < S_) {
                const float inv = 1.0f / (psum[h] + sPS[wq * QPW + lr + 8 * h]);
                float* dst = og + (((size_t)batch * S_ + t) * NH_ + head) * HD_;
                #pragma unroll
                for (int nt = 0; nt < 8; ++nt) {
                    float2 s2 = *reinterpret_cast<const float2*>(
                        so + (lr + 8 * h) * OSTR + nt * 8 + 2 * lc);
                    float2 o;
                    o.x = (Oacc[nt][2 * h + 0] + s2.x) * inv;
                    o.y = (Oacc[nt][2 * h + 1] + s2.y) * inv;
                    *reinterpret_cast<float2*>(dst + nt * 8 + 2 * lc) = o;
                }
            }
        }
    }
}

extern "C" void kernel_launch(void* const* d_in, const int* in_sizes, int n_in,
                              void* d_out, int out_size)
{
    const float* q = (const float*)d_in[0];
    const float* k = (const float*)d_in[1];
    const float* v = (const float*)d_in[2];
    float* o = (float*)d_out;

    (void)cudaFuncSetAttribute(window_attn_mma,
                               cudaFuncAttributeMaxDynamicSharedMemorySize,
                               SMEM_FLOATS * (int)sizeof(float));

    window_attn_mma<<<B_ * NH_ * NCHUNK, 512, SMEM_FLOATS * (int)sizeof(float)>>>(q, k, v, o);
}

// round 13
// speedup vs baseline: 1.2852x; 1.0428x over previous
#include <cuda_runtime.h>
#include <cstdint>
#include <cstddef>

// ---------------- problem constants ----------------
#define B_      8
#define S_      4094
#define NH_     8
#define HD_     64
#define TQ      128        // queries per CTA (M)
#define NKEY    256        // padded key rows per CTA (254 real + 2 always-masked)
#define NCHUNK  32         // ceil(4094/128)
#define QPW     16         // query rows per warp
#define KPW     48         // keys per warp (band-aware: 3 warps cover the 144-key band)
#define NT1     6          // n-tiles of 8 keys per warp
#define THREADS 768        // 24 warps = 8 query groups x 3 key thirds

// ---------------- packed smem layout ----------------
// All tiles store float2 PAIRS {x[k], x[k+4]} so each MMA fragment operand is
// one LDS.64. Strides chosen for conflict-free 64-bit half-warp transactions.
#define QP2 36             // pQ row stride in float2 (72 floats)
#define KP2 36             // pK row stride in float2
#define VP2 68             // pV row stride in float2 (136 floats)
#define OSTR 68            // staging stride for cross-third O reduction

#define OFF_Q  0                               // 128*72  =  9216 floats
#define OFF_K  (TQ * QP2 * 2)                  // 9216; 256*72 = 18432 floats
#define OFF_V  (OFF_K + NKEY * KP2 * 2)        // 27648; 128*136 = 17408 floats
#define OFF_PS (OFF_V + (NKEY / 2) * VP2 * 2)  // 45056; 2*128 = 256 floats
#define SMEM_FLOATS (OFF_PS + 2 * TQ)          // 45312 floats = 181248 B
// O staging reuses the DEAD pQ (third 1) and pK (third 2) regions after the
// mainloop: 8 groups * 16 rows * OSTR = 8704 floats each (fits 9216 / 18432).
#define OPW    (QPW * OSTR)                    // 1088 floats per group

// ---------------- helpers ----------------
__device__ __forceinline__ float to_tf32(float x) {
    uint32_t u;
    asm("cvt.rna.tf32.f32 %0, %1;" : "=r"(u) : "f"(x));
    return __uint_as_float(u);
}
__device__ __forceinline__ uint32_t fb(float x) { return __float_as_uint(x); }

// m16n8k8 tf32 mma, fp32 accumulate (family-portable, sm_80+)
__device__ __forceinline__ void mma8(float* d, const uint32_t* a, const uint32_t* b) {
    asm volatile(
        "mma.sync.aligned.m16n8k8.row.col.f32.tf32.tf32.f32 "
        "{%0,%1,%2,%3}, {%4,%5,%6,%7}, {%8,%9}, {%0,%1,%2,%3};"
        : "+f"(d[0]), "+f"(d[1]), "+f"(d[2]), "+f"(d[3])
        : "r"(a[0]), "r"(a[1]), "r"(a[2]), "r"(a[3]), "r"(b[0]), "r"(b[1]));
}

// ---------------- kernel ----------------
__global__ __launch_bounds__(THREADS, 1)
void window_attn_mma(const float* __restrict__ qg, const float* __restrict__ kg,
                     const float* __restrict__ vg, float* __restrict__ og)
{
    extern __shared__ float sm[];
    float2* pQ = reinterpret_cast<float2*>(sm + OFF_Q);
    float2* pK = reinterpret_cast<float2*>(sm + OFF_K);
    float2* pV = reinterpret_cast<float2*>(sm + OFF_V);
    float*  sPS = sm + OFF_PS;                 // [2][128] partial sums (thirds 1,2)

    const int bx    = blockIdx.x;
    const int chunk = bx & (NCHUNK - 1);
    const int head  = (bx >> 5) & (NH_ - 1);
    const int batch = bx >> 8;
    const int t0    = chunk * TQ;

    const int tid  = threadIdx.x;
    const int w    = tid >> 5;
    const int lane = tid & 31;
    const int lr   = lane >> 2;   // row-in-fragment
    const int lc   = lane & 3;    // col-in-fragment
    const int wq   = w & 7;       // query group (16 rows)
    const int kh   = w >> 3;      // key third of the band (48 keys each; 0,1,2)

    // ---- fill packed Q: pQ[m][4g+j] = {Q[m][8g+j], Q[m][8g+j+4]}, scaled 1/8
    for (int idx = tid; idx < TQ * 8; idx += THREADS) {
        int m = idx >> 3, g = idx & 7;
        int t = t0 + m;
        float4 a = make_float4(0.f, 0.f, 0.f, 0.f), b = a;
        if (t < S_) {
            const float4* src = reinterpret_cast<const float4*>(
                qg + (((size_t)batch * S_ + t) * NH_ + head) * HD_ + 8 * g);
            a = src[0]; b = src[1];
            a.x = to_tf32(a.x * 0.125f); a.y = to_tf32(a.y * 0.125f);
            a.z = to_tf32(a.z * 0.125f); a.w = to_tf32(a.w * 0.125f);
            b.x = to_tf32(b.x * 0.125f); b.y = to_tf32(b.y * 0.125f);
            b.z = to_tf32(b.z * 0.125f); b.w = to_tf32(b.w * 0.125f);
        }
        float* dst = sm + OFF_Q + m * (QP2 * 2) + 8 * g;
        reinterpret_cast<float4*>(dst)[0] = make_float4(a.x, b.x, a.y, b.y);
        reinterpret_cast<float4*>(dst)[1] = make_float4(a.z, b.z, a.w, b.w);
    }
    // ---- fill packed K; out-of-sequence rows ZERO (reference's zero padding)
    for (int idx = tid; idx < NKEY * 8; idx += THREADS) {
        int r = idx >> 3, g = idx & 7;
        int gl = t0 - 63 + r;
        float4 a = make_float4(0.f, 0.f, 0.f, 0.f), b = a;
        if (gl >= 0 && gl < S_) {
            const float4* src = reinterpret_cast<const float4*>(
                kg + (((size_t)batch * S_ + gl) * NH_ + head) * HD_ + 8 * g);
            a = src[0]; b = src[1];
            a.x = to_tf32(a.x); a.y = to_tf32(a.y); a.z = to_tf32(a.z); a.w = to_tf32(a.w);
            b.x = to_tf32(b.x); b.y = to_tf32(b.y); b.z = to_tf32(b.z); b.w = to_tf32(b.w);
        }
        float* dst = sm + OFF_K + r * (KP2 * 2) + 8 * g;
        reinterpret_cast<float4*>(dst)[0] = make_float4(a.x, b.x, a.y, b.y);
        reinterpret_cast<float4*>(dst)[1] = make_float4(a.z, b.z, a.w, b.w);
    }
    // ---- fill packed V: pV[p][d] = {V[key][d], V[key+4][d]},
    //      key = 8*(p>>2)+(p&3). Out-of-sequence rows ZERO.
    for (int idx = tid; idx < (NKEY / 2) * 16; idx += THREADS) {
        int p = idx >> 4, dg = idx & 15;
        int k1 = 8 * (p >> 2) + (p & 3);
        int g1 = t0 - 63 + k1, g2 = g1 + 4;
        float4 a = make_float4(0.f, 0.f, 0.f, 0.f), b = a;
        if (g1 >= 0 && g1 < S_) {
            a = reinterpret_cast<const float4*>(
                vg + (((size_t)batch * S_ + g1) * NH_ + head) * HD_ + 4 * dg)[0];
            a.x = to_tf32(a.x); a.y = to_tf32(a.y); a.z = to_tf32(a.z); a.w = to_tf32(a.w);
        }
        if (g2 >= 0 && g2 < S_) {
            b = reinterpret_cast<const float4*>(
                vg + (((size_t)batch * S_ + g2) * NH_ + head) * HD_ + 4 * dg)[0];
            b.x = to_tf32(b.x); b.y = to_tf32(b.y); b.z = to_tf32(b.z); b.w = to_tf32(b.w);
        }
        float* dst = sm + OFF_V + p * (VP2 * 2) + 8 * dg;
        reinterpret_cast<float4*>(dst)[0] = make_float4(a.x, b.x, a.y, b.y);
        reinterpret_cast<float4*>(dst)[1] = make_float4(a.z, b.z, a.w, b.w);
    }
    __syncthreads();

    const int qbase = wq * QPW;                // this warp's first query row
    const int kbase = qbase + kh * KPW;        // this warp's first key row:
                                               //   band [qbase, qbase+144) in thirds;
                                               //   every nonzero-mask key covered once
    const int srcA  = (lr << 2) + (lc >> 1);   // shuffle sources for P permute
    const int srcB  = srcA + 2;
    const bool odd  = lc & 1;

    float Oacc[8][4];
    #pragma unroll
    for (int nt = 0; nt < 8; ++nt)
        #pragma unroll
        for (int e = 0; e < 4; ++e) Oacc[nt][e] = 0.f;
    float psum[2] = {0.f, 0.f};

    // ---- GEMM1: S[16 x 48] = Q_warp @ K_third^T (6 n-tiles of 8 keys)
    float Sacc[NT1][4];
    #pragma unroll
    for (int nt = 0; nt < NT1; ++nt)
        #pragma unroll
        for (int e = 0; e < 4; ++e) Sacc[nt][e] = 0.f;

    #pragma unroll
    for (int kk = 0; kk < 8; ++kk) {
        uint32_t afr[4];
        {
            const float2* qp = pQ + (qbase + lr) * QP2 + kk * 4 + lc;
            float2 fa = qp[0];            // {Q[m][k],   Q[m][k+4]}
            float2 fc = qp[8 * QP2];      // {Q[m+8][k], Q[m+8][k+4]}
            afr[0] = fb(fa.x); afr[1] = fb(fc.x);
            afr[2] = fb(fa.y); afr[3] = fb(fc.y);
        }
        #pragma unroll
        for (int nt = 0; nt < NT1; ++nt) {
            float2 bv = pK[(kbase + nt * 8 + lr) * KP2 + kk * 4 + lc];
            uint32_t bfr[2] = { fb(bv.x), fb(bv.y) };
            mma8(Sacc[nt], afr, bfr);
        }
    }

    // ---- band mask + exp (tf32-rounded) + row-sum partials, in registers
    #pragma unroll
    for (int h = 0; h < 2; ++h) {
        const int m = qbase + lr + 8 * h;            // local query idx
        #pragma unroll
        for (int nt = 0; nt < NT1; ++nt) {
            const int j0 = kbase + nt * 8 + 2 * lc;  // key window idx
            float s0 = Sacc[nt][2 * h + 0];
            float s1 = Sacc[nt][2 * h + 1];
            float p0 = (j0     >= m && j0     <= m + 126) ? __expf(s0) : 0.f;
            float p1 = (j0 + 1 >= m && j0 + 1 <= m + 126) ? __expf(s1) : 0.f;
            psum[h] += p0 + p1;
            Sacc[nt][2 * h + 0] = to_tf32(p0);
            Sacc[nt][2 * h + 1] = to_tf32(p1);
        }
    }

    // ---- GEMM2: O[16 x 64] += P_third @ V_third (K = 48 keys, 6 k-groups).
    // A-fragment from D-fragment P via intra-warp shuffles.
    #pragma unroll
    for (int kk = 0; kk < NT1; ++kk) {
        float q0 = __shfl_sync(0xffffffffu, Sacc[kk][0], srcA);
        float q1 = __shfl_sync(0xffffffffu, Sacc[kk][1], srcA);
        float q2 = __shfl_sync(0xffffffffu, Sacc[kk][2], srcA);
        float q3 = __shfl_sync(0xffffffffu, Sacc[kk][3], srcA);
        float r0 = __shfl_sync(0xffffffffu, Sacc[kk][0], srcB);
        float r1 = __shfl_sync(0xffffffffu, Sacc[kk][1], srcB);
        float r2 = __shfl_sync(0xffffffffu, Sacc[kk][2], srcB);
        float r3 = __shfl_sync(0xffffffffu, Sacc[kk][3], srcB);
        uint32_t afr[4];
        afr[0] = fb(odd ? q1 : q0);
        afr[1] = fb(odd ? q3 : q2);
        afr[2] = fb(odd ? r1 : r0);
        afr[3] = fb(odd ? r3 : r2);
        const int prow = (kbase >> 1) + kk * 4 + lc;   // packed V pair-row
        #pragma unroll
        for (int nt = 0; nt < 8; ++nt) {
            float2 bv = pV[prow * VP2 + nt * 8 + lr];
            uint32_t bfr[2] = { fb(bv.x), fb(bv.y) };
            mma8(Oacc[nt], afr, bfr);
        }
    }

    // ---- row-sum partials: reduce across the 4 lanes of each quad
    #pragma unroll
    for (int h = 0; h < 2; ++h) {
        float s = psum[h];
        s += __shfl_xor_sync(0xffffffffu, s, 1);
        s += __shfl_xor_sync(0xffffffffu, s, 2);
        psum[h] = s;
    }

    // ---- cross-third combine. Staging reuses the DEAD pQ/pK regions, so all
    // warps must be past their pQ/pK reads first.
    __syncthreads();
    if (kh > 0) {
        float* so = sm + (kh == 1 ? OFF_Q : OFF_K) + wq * OPW;
        float* ps = sPS + (kh - 1) * TQ;
        #pragma unroll
        for (int h = 0; h < 2; ++h) {
            #pragma unroll
            for (int nt = 0; nt < 8; ++nt) {
                float2 o;
                o.x = Oacc[nt][2 * h + 0];
                o.y = Oacc[nt][2 * h + 1];
                *reinterpret_cast<float2*>(so + (lr + 8 * h) * OSTR + nt * 8 + 2 * lc) = o;
            }
            if (lc == 0) ps[wq * QPW + lr + 8 * h] = psum[h];
        }
    }
    __syncthreads();

    // ---- key-third-0 warps add both staged thirds, normalize, store
    if (kh == 0) {
        const float* so1 = sm + OFF_Q + wq * OPW;
        const float* so2 = sm + OFF_K + wq * OPW;
        #pragma unroll
        for (int h = 0; h < 2; ++h) {
            const int m = qbase + lr + 8 * h;
            const int t = t0 + m;
            if (t < S_) {
                const float inv = 1.0f /
                    (psum[h] + sPS[wq * QPW + lr + 8 * h] + sPS[TQ + wq * QPW + lr + 8 * h]);
                float* dst = og + (((size_t)batch * S_ + t) * NH_ + head) * HD_;
                #pragma unroll
                for (int nt = 0; nt < 8; ++nt) {
                    const int off = (lr + 8 * h) * OSTR + nt * 8 + 2 * lc;
                    float2 s1 = *reinterpret_cast<const float2*>(so1 + off);
                    float2 s2 = *reinterpret_cast<const float2*>(so2 + off);
                    float2 o;
                    o.x = (Oacc[nt][2 * h + 0] + s1.x + s2.x) * inv;
                    o.y = (Oacc[nt][2 * h + 1] + s1.y + s2.y) * inv;
                    *reinterpret_cast<float2*>(dst + nt * 8 + 2 * lc) = o;
                }
            }
        }
    }
}

extern "C" void kernel_launch(void* const* d_in, const int* in_sizes, int n_in,
                              void* d_out, int out_size)
{
    const float* q = (const float*)d_in[0];
    const float* k = (const float*)d_in[1];
    const float* v = (const float*)d_in[2];
    float* o = (float*)d_out;

    (void)cudaFuncSetAttribute(window_attn_mma,
                               cudaFuncAttributeMaxDynamicSharedMemorySize,
                               SMEM_FLOATS * (int)sizeof(float));

    window_attn_mma<<<B_ * NH_ * NCHUNK, THREADS, SMEM_FLOATS * (int)sizeof(float)>>>(q, k, v, o);
}

// round 14
// speedup vs baseline: 1.9044x; 1.4818x over previous
#include <cuda_runtime.h>
#include <cuda_fp16.h>
#include <cstdint>
#include <cstddef>

// ---------------- problem constants ----------------
#define B_      8
#define S_      4094
#define NH_     8
#define HD_     64
#define TQ      128        // queries per CTA (M)
#define NKEY    256        // padded key rows per CTA (254 real + 2 always-masked)
#define NCHUNK  32         // ceil(4094/128)
#define QPW     16         // query rows per warp
#define KPW     48         // keys per warp (band thirds: 3 warps cover 144-key band)
#define NT1     6          // n-tiles of 8 keys per warp (GEMM1)
#define THREADS 768        // 24 warps = 8 query groups x 3 key thirds

// ---------------- packed fp16 smem layout ----------------
// pQ/pK rows: per k16-group kg, 4 uint2 (lc=0..3), each = {h2(k0,k0+1), h2(k0+8,k0+9)}
// with k0 = 16*kg + 2*lc. Row stride 20 uint2 (16 data + 4 pad): Δrow ≡ 4 (mod 16)
// bank-pairs -> conflict-free LDS.64 B/A fragment loads.
// pV rows: r = 4*KG + lc2 holds, per d, uint2 = {h2(V[j0][d],V[j0+1][d]),
// h2(V[j0+8][d],V[j0+9][d])}, j0 = 16*KG + 2*lc2. Row stride 68 uint2: Δlc ≡ 4.
#define QSTR16 20          // uint2 per Q row
#define KSTR16 20          // uint2 per K row
#define VSTR16 68          // uint2 per V pair-row
#define NVROW  64          // V pair-rows (NKEY/16*4)
#define OSTR   68          // fp32 staging stride (cross-third O reduction)
#define OPW    (QPW * OSTR)            // 1088 floats per query group

#define OFF_Q16 0                      // 128*20*8 = 20480 B
#define OFF_K16 20480                  // 256*20*8 = 40960 B
#define OFF_V16 61440                  // 64*68*8  = 34816 B
#define OFF_PS  96256                  // 2*128 floats = 1024 B
#define SMEM_BYTES 97280
// Staging reuses DEAD regions after the mainloop:
//   third 1 -> pK region (40960 B >= 8*1088*4 = 34816 B)
//   third 2 -> pV region (34816 B == 34816 B)

// ---------------- helpers ----------------
__device__ __forceinline__ uint32_t h2u(float lo, float hi) {
    uint32_t u;  // PTX cvt.f16x2: first source -> upper half
    asm("cvt.rn.f16x2.f32 %0, %1, %2;" : "=r"(u) : "f"(hi), "f"(lo));
    return u;
}

// m16n8k16 fp16 mma, fp32 accumulate (family-portable, sm_80+)
__device__ __forceinline__ void mma16(float* d, const uint32_t* a,
                                      uint32_t b0, uint32_t b1) {
    asm volatile(
        "mma.sync.aligned.m16n8k16.row.col.f32.f16.f16.f32 "
        "{%0,%1,%2,%3}, {%4,%5,%6,%7}, {%8,%9}, {%0,%1,%2,%3};"
        : "+f"(d[0]), "+f"(d[1]), "+f"(d[2]), "+f"(d[3])
        : "r"(a[0]), "r"(a[1]), "r"(a[2]), "r"(a[3]), "r"(b0), "r"(b1));
}

// ---------------- kernel ----------------
__global__ __launch_bounds__(THREADS, 1)
void window_attn_mma(const float* __restrict__ qg, const float* __restrict__ kg,
                     const float* __restrict__ vg, float* __restrict__ og)
{
    extern __shared__ char sm[];
    uint2* pQ  = reinterpret_cast<uint2*>(sm + OFF_Q16);
    uint2* pK  = reinterpret_cast<uint2*>(sm + OFF_K16);
    uint2* pV  = reinterpret_cast<uint2*>(sm + OFF_V16);
    float* sPS = reinterpret_cast<float*>(sm + OFF_PS);

    const int bx    = blockIdx.x;
    const int chunk = bx & (NCHUNK - 1);
    const int head  = (bx >> 5) & (NH_ - 1);
    const int batch = bx >> 8;
    const int t0    = chunk * TQ;

    const int tid  = threadIdx.x;
    const int w    = tid >> 5;
    const int lane = tid & 31;
    const int lr   = lane >> 2;   // row-in-fragment
    const int lc   = lane & 3;    // col-in-fragment
    const int wq   = w & 7;       // query group (16 rows)
    const int kh   = w >> 3;      // key third of the band (48 keys; 0,1,2)

    // ---- fill packed fp16 Q (scaled 1/8). One (row, k16-group) per item.
    for (int idx = tid; idx < TQ * 4; idx += THREADS) {
        int m = idx >> 2, g = idx & 3;
        int t = t0 + m;
        float v[16];
        #pragma unroll
        for (int i = 0; i < 16; ++i) v[i] = 0.f;
        if (t < S_) {
            const float4* src = reinterpret_cast<const float4*>(
                qg + (((size_t)batch * S_ + t) * NH_ + head) * HD_ + 16 * g);
            #pragma unroll
            for (int i = 0; i < 4; ++i) {
                float4 f = src[i];
                v[4*i+0] = f.x * 0.125f; v[4*i+1] = f.y * 0.125f;
                v[4*i+2] = f.z * 0.125f; v[4*i+3] = f.w * 0.125f;
            }
        }
        uint2 u[4];
        #pragma unroll
        for (int c = 0; c < 4; ++c)
            u[c] = make_uint2(h2u(v[2*c], v[2*c+1]), h2u(v[2*c+8], v[2*c+9]));
        uint4* dst = reinterpret_cast<uint4*>(pQ + m * QSTR16 + g * 4);
        dst[0] = make_uint4(u[0].x, u[0].y, u[1].x, u[1].y);
        dst[1] = make_uint4(u[2].x, u[2].y, u[3].x, u[3].y);
    }
    // ---- fill packed fp16 K; out-of-sequence rows ZERO (reference padding)
    for (int idx = tid; idx < NKEY * 4; idx += THREADS) {
        int r = idx >> 2, g = idx & 3;
        int gl = t0 - 63 + r;
        float v[16];
        #pragma unroll
        for (int i = 0; i < 16; ++i) v[i] = 0.f;
        if (gl >= 0 && gl < S_) {
            const float4* src = reinterpret_cast<const float4*>(
                kg + (((size_t)batch * S_ + gl) * NH_ + head) * HD_ + 16 * g);
            #pragma unroll
            for (int i = 0; i < 4; ++i) {
                float4 f = src[i];
                v[4*i+0] = f.x; v[4*i+1] = f.y; v[4*i+2] = f.z; v[4*i+3] = f.w;
            }
        }
        uint2 u[4];
        #pragma unroll
        for (int c = 0; c < 4; ++c)
            u[c] = make_uint2(h2u(v[2*c], v[2*c+1]), h2u(v[2*c+8], v[2*c+9]));
        uint4* dst = reinterpret_cast<uint4*>(pK + r * KSTR16 + g * 4);
        dst[0] = make_uint4(u[0].x, u[0].y, u[1].x, u[1].y);
        dst[1] = make_uint4(u[2].x, u[2].y, u[3].x, u[3].y);
    }
    // ---- fill packed fp16 V: item = (pair-row r, 8-dim chunk c)
    for (int idx = tid; idx < NVROW * 8; idx += THREADS) {
        int r = idx >> 3, c = idx & 7;
        int kgp = r >> 2, lc2 = r & 3;
        int j0 = 16 * kgp + 2 * lc2;
        float va[8], vb[8], vc[8], vd[8];
        #pragma unroll
        for (int i = 0; i < 8; ++i) { va[i]=0.f; vb[i]=0.f; vc[i]=0.f; vd[i]=0.f; }
        int ga = t0 - 63 + j0;
        #pragma unroll
        for (int rr = 0; rr < 4; ++rr) {
            int gl = ga + ((rr & 1) ? 1 : 0) + ((rr >> 1) ? 8 : 0);
            float* dstv = (rr == 0) ? va : (rr == 1) ? vb : (rr == 2) ? vc : vd;
            if (gl >= 0 && gl < S_) {
                const float4* src = reinterpret_cast<const float4*>(
                    vg + (((size_t)batch * S_ + gl) * NH_ + head) * HD_ + 8 * c);
                float4 f0 = src[0], f1 = src[1];
                dstv[0]=f0.x; dstv[1]=f0.y; dstv[2]=f0.z; dstv[3]=f0.w;
                dstv[4]=f1.x; dstv[5]=f1.y; dstv[6]=f1.z; dstv[7]=f1.w;
            }
        }
        uint2 u[8];
        #pragma unroll
        for (int i = 0; i < 8; ++i)
            u[i] = make_uint2(h2u(va[i], vb[i]), h2u(vc[i], vd[i]));
        uint4* dst = reinterpret_cast<uint4*>(pV + r * VSTR16 + 8 * c);
        #pragma unroll
        for (int i = 0; i < 4; ++i)
            dst[i] = make_uint4(u[2*i].x, u[2*i].y, u[2*i+1].x, u[2*i+1].y);
    }
    __syncthreads();

    const int qbase = wq * QPW;          // this warp's first query row
    const int kbase = qbase + kh * KPW;  // band [qbase, qbase+144) in thirds

    float Oacc[8][4];
    #pragma unroll
    for (int nt = 0; nt < 8; ++nt)
        #pragma unroll
        for (int e = 0; e < 4; ++e) Oacc[nt][e] = 0.f;
    float psum[2] = {0.f, 0.f};

    // ---- GEMM1: S[16 x 48] = Q_warp @ K_third^T  (4 k16-groups x 6 n-tiles)
    float Sacc[NT1][4];
    #pragma unroll
    for (int nt = 0; nt < NT1; ++nt)
        #pragma unroll
        for (int e = 0; e < 4; ++e) Sacc[nt][e] = 0.f;

    #pragma unroll
    for (int kg = 0; kg < 4; ++kg) {
        uint2 qa = pQ[(qbase + lr)     * QSTR16 + kg * 4 + lc];
        uint2 qb = pQ[(qbase + lr + 8) * QSTR16 + kg * 4 + lc];
        uint32_t afr[4] = { qa.x, qb.x, qa.y, qb.y };
        #pragma unroll
        for (int nt = 0; nt < NT1; ++nt) {
            uint2 bv = pK[(kbase + nt * 8 + lr) * KSTR16 + kg * 4 + lc];
            mma16(Sacc[nt], afr, bv.x, bv.y);
        }
    }

    // ---- band mask + exp + row-sum partials, in registers (fp32)
    #pragma unroll
    for (int h = 0; h < 2; ++h) {
        const int m = qbase + lr + 8 * h;            // local query idx
        #pragma unroll
        for (int nt = 0; nt < NT1; ++nt) {
            const int j0 = kbase + nt * 8 + 2 * lc;  // key window idx
            float s0 = Sacc[nt][2 * h + 0];
            float s1 = Sacc[nt][2 * h + 1];
            float p0 = (j0     >= m && j0     <= m + 126) ? __expf(s0) : 0.f;
            float p1 = (j0 + 1 >= m && j0 + 1 <= m + 126) ? __expf(s1) : 0.f;
            psum[h] += p0 + p1;
            Sacc[nt][2 * h + 0] = p0;
            Sacc[nt][2 * h + 1] = p1;
        }
    }

    // ---- GEMM2: O[16 x 64] += P_third @ V_third  (3 k16-groups x 8 n-tiles).
    // fp16 k16 A-fragment == pairs of GEMM1 D-tiles: NO shuffle, NO smem.
    #pragma unroll
    for (int kg2 = 0; kg2 < 3; ++kg2) {
        uint32_t afr[4];
        afr[0] = h2u(Sacc[2*kg2  ][0], Sacc[2*kg2  ][1]);
        afr[1] = h2u(Sacc[2*kg2  ][2], Sacc[2*kg2  ][3]);
        afr[2] = h2u(Sacc[2*kg2+1][0], Sacc[2*kg2+1][1]);
        afr[3] = h2u(Sacc[2*kg2+1][2], Sacc[2*kg2+1][3]);
        const int r = ((kbase >> 4) + kg2) * 4 + lc;   // pV pair-row
        #pragma unroll
        for (int nt = 0; nt < 8; ++nt) {
            uint2 bv = pV[r * VSTR16 + nt * 8 + lr];
            mma16(Oacc[nt], afr, bv.x, bv.y);
        }
    }

    // ---- row-sum partials: reduce across the 4 lanes of each quad
    #pragma unroll
    for (int h = 0; h < 2; ++h) {
        float s = psum[h];
        s += __shfl_xor_sync(0xffffffffu, s, 1);
        s += __shfl_xor_sync(0xffffffffu, s, 2);
        psum[h] = s;
    }

    // ---- cross-third combine. Staging reuses DEAD pK/pV regions, so all
    // warps must be past their mainloop smem reads first.
    __syncthreads();
    if (kh > 0) {
        float* so = reinterpret_cast<float*>(sm + (kh == 1 ? OFF_K16 : OFF_V16))
                    + wq * OPW;
        float* ps = sPS + (kh - 1) * TQ;
        #pragma unroll
        for (int h = 0; h < 2; ++h) {
            #pragma unroll
            for (int nt = 0; nt < 8; ++nt) {
                float2 o;
                o.x = Oacc[nt][2 * h + 0];
                o.y = Oacc[nt][2 * h + 1];
                *reinterpret_cast<float2*>(so + (lr + 8 * h) * OSTR + nt * 8 + 2 * lc) = o;
            }
            if (lc == 0) ps[wq * QPW + lr + 8 * h] = psum[h];
        }
    }
    __syncthreads();

    // ---- key-third-0 warps add both staged thirds, normalize, store
    if (kh == 0) {
        const float* so1 = reinterpret_cast<const float*>(sm + OFF_K16) + wq * OPW;
        const float* so2 = reinterpret_cast<const float*>(sm + OFF_V16) + wq * OPW;
        #pragma unroll
        for (int h = 0; h < 2; ++h) {
            const int m = qbase + lr + 8 * h;
            const int t = t0 + m;
            if (t < S_) {
                const float inv = 1.0f /
                    (psum[h] + sPS[wq * QPW + lr + 8 * h] + sPS[TQ + wq * QPW + lr + 8 * h]);
                float* dst = og + (((size_t)batch * S_ + t) * NH_ + head) * HD_;
                #pragma unroll
                for (int nt = 0; nt < 8; ++nt) {
                    const int off = (lr + 8 * h) * OSTR + nt * 8 + 2 * lc;
                    float2 s1 = *reinterpret_cast<const float2*>(so1 + off);
                    float2 s2 = *reinterpret_cast<const float2*>(so2 + off);
                    float2 o;
                    o.x = (Oacc[nt][2 * h + 0] + s1.x + s2.x) * inv;
                    o.y = (Oacc[nt][2 * h + 1] + s1.y + s2.y) * inv;
                    *reinterpret_cast<float2*>(dst + nt * 8 + 2 * lc) = o;
                }
            }
        }
    }
}

extern "C" void kernel_launch(void* const* d_in, const int* in_sizes, int n_in,
                              void* d_out, int out_size)
{
    const float* q = (const float*)d_in[0];
    const float* k = (const float*)d_in[1];
    const float* v = (const float*)d_in[2];
    float* o = (float*)d_out;

    (void)cudaFuncSetAttribute(window_attn_mma,
                               cudaFuncAttributeMaxDynamicSharedMemorySize,
                               SMEM_BYTES);

    window_attn_mma<<<B_ * NH_ * NCHUNK, THREADS, SMEM_BYTES>>>(q, k, v, o);
}

// round 15
// speedup vs baseline: 2.2357x; 1.1740x over previous
#include <cuda_runtime.h>
#include <cuda_fp16.h>
#include <cstdint>
#include <cstddef>

// ---------------- problem constants ----------------
#define B_      8
#define S_      4094
#define NH_     8
#define HD_     64
#define TQ      256        // queries per CTA (8 groups of 32)
#define NKEY2   384        // key rows per CTA (256 + 126 halo, padded)
#define NCHUNK  16         // 4094 / 256 -> 16 chunks
#define GQ      32         // queries per group (2 m-tiles)
#define KPW     80         // keys per warp (2 halves cover the 158-key band)
#define THREADS 512        // 16 warps = 8 groups x 2 key halves

// Q pre-scale: 1/sqrt(64) * log2(e)  (exp(s) == exp2(s'); softmax unchanged)
#define QSCALE  0.180336879f

// ---------------- packed fp16 smem layout ----------------
// pQ/pK rows: per k16-group kg, 4 uint2 (lc=0..3): {h2(k0,k0+1), h2(k0+8,k0+9)},
// k0 = 16*kg + 2*lc. Row stride 20 uint2 -> conflict-free LDS.64.
// pV pair-rows r = 4*KG + lc2: per dim d, uint2 = {h2(V[j0][d],V[j0+1][d]),
// h2(V[j0+8][d],V[j0+9][d])}, j0 = 16*KG + 2*lc2. Row stride 68 uint2.
#define QSTR16 20
#define KSTR16 20
#define VSTR16 68
#define NVROW  96          // NKEY2/16*4
#define OSTR   68          // fp32 staging stride
#define OPG    (GQ * OSTR) // 2176 floats staged per group

#define OFF_Q16 0                      // 256*20*8 = 40960 B
#define OFF_K16 40960                  // 384*20*8 = 61440 B
#define OFF_V16 102400                 // 96*68*8  = 52224 B
#define OFF_PS  154624                 // 256 floats = 1024 B
#define SMEM_BYTES 155648
// O staging reuses the DEAD pQ(+pK) region after the mainloop:
// group g at byte offset g*OPG*4 (8*8704 = 69632 <= 102400 dead bytes).

// ---------------- helpers ----------------
__device__ __forceinline__ uint32_t h2u(float lo, float hi) {
    uint32_t u;  // first source -> upper half
    asm("cvt.rn.f16x2.f32 %0, %1, %2;" : "=r"(u) : "f"(hi), "f"(lo));
    return u;
}

// m16n8k16 fp16 mma, fp32 accumulate (family-portable, sm_80+)
__device__ __forceinline__ void mma16(float* d, const uint32_t* a,
                                      uint32_t b0, uint32_t b1) {
    asm volatile(
        "mma.sync.aligned.m16n8k16.row.col.f32.f16.f16.f32 "
        "{%0,%1,%2,%3}, {%4,%5,%6,%7}, {%8,%9}, {%0,%1,%2,%3};"
        : "+f"(d[0]), "+f"(d[1]), "+f"(d[2]), "+f"(d[3])
        : "r"(a[0]), "r"(a[1]), "r"(a[2]), "r"(a[3]), "r"(b0), "r"(b1));
}

// ---------------- kernel ----------------
__global__ __launch_bounds__(THREADS, 1)
void window_attn_mma(const float* __restrict__ qg, const float* __restrict__ kg,
                     const float* __restrict__ vg, float* __restrict__ og)
{
    extern __shared__ char sm[];
    uint2* pQ  = reinterpret_cast<uint2*>(sm + OFF_Q16);
    uint2* pK  = reinterpret_cast<uint2*>(sm + OFF_K16);
    uint2* pV  = reinterpret_cast<uint2*>(sm + OFF_V16);
    float* sPS = reinterpret_cast<float*>(sm + OFF_PS);

    const int bx    = blockIdx.x;
    const int chunk = bx & (NCHUNK - 1);
    const int head  = (bx >> 4) & (NH_ - 1);
    const int batch = bx >> 7;
    const int t0    = chunk * TQ;

    const int tid  = threadIdx.x;
    const int w    = tid >> 5;
    const int lane = tid & 31;
    const int lr   = lane >> 2;   // row-in-fragment
    const int lc   = lane & 3;    // col-in-fragment
    const int wq   = w & 7;       // query group (32 rows)
    const int kh   = w >> 3;      // key half of the band (80 keys; 0,1)

    // ---- fill packed fp16 Q (scaled by 1/8*log2e). One (row, k16-group)/item.
    for (int idx = tid; idx < TQ * 4; idx += THREADS) {
        int m = idx >> 2, g = idx & 3;
        int t = t0 + m;
        float v[16];
        #pragma unroll
        for (int i = 0; i < 16; ++i) v[i] = 0.f;
        if (t < S_) {
            const float4* src = reinterpret_cast<const float4*>(
                qg + (((size_t)batch * S_ + t) * NH_ + head) * HD_ + 16 * g);
            #pragma unroll
            for (int i = 0; i < 4; ++i) {
                float4 f = src[i];
                v[4*i+0] = f.x * QSCALE; v[4*i+1] = f.y * QSCALE;
                v[4*i+2] = f.z * QSCALE; v[4*i+3] = f.w * QSCALE;
            }
        }
        uint2 u[4];
        #pragma unroll
        for (int c = 0; c < 4; ++c)
            u[c] = make_uint2(h2u(v[2*c], v[2*c+1]), h2u(v[2*c+8], v[2*c+9]));
        uint4* dst = reinterpret_cast<uint4*>(pQ + m * QSTR16 + g * 4);
        dst[0] = make_uint4(u[0].x, u[0].y, u[1].x, u[1].y);
        dst[1] = make_uint4(u[2].x, u[2].y, u[3].x, u[3].y);
    }
    // ---- fill packed fp16 K; out-of-sequence rows ZERO (reference padding)
    for (int idx = tid; idx < NKEY2 * 4; idx += THREADS) {
        int r = idx >> 2, g = idx & 3;
        int gl = t0 - 63 + r;
        float v[16];
        #pragma unroll
        for (int i = 0; i < 16; ++i) v[i] = 0.f;
        if (gl >= 0 && gl < S_) {
            const float4* src = reinterpret_cast<const float4*>(
                kg + (((size_t)batch * S_ + gl) * NH_ + head) * HD_ + 16 * g);
            #pragma unroll
            for (int i = 0; i < 4; ++i) {
                float4 f = src[i];
                v[4*i+0] = f.x; v[4*i+1] = f.y; v[4*i+2] = f.z; v[4*i+3] = f.w;
            }
        }
        uint2 u[4];
        #pragma unroll
        for (int c = 0; c < 4; ++c)
            u[c] = make_uint2(h2u(v[2*c], v[2*c+1]), h2u(v[2*c+8], v[2*c+9]));
        uint4* dst = reinterpret_cast<uint4*>(pK + r * KSTR16 + g * 4);
        dst[0] = make_uint4(u[0].x, u[0].y, u[1].x, u[1].y);
        dst[1] = make_uint4(u[2].x, u[2].y, u[3].x, u[3].y);
    }
    // ---- fill packed fp16 V: item = (pair-row r, 8-dim chunk c)
    for (int idx = tid; idx < NVROW * 8; idx += THREADS) {
        int r = idx >> 3, c = idx & 7;
        int kgp = r >> 2, lc2 = r & 3;
        int j0 = 16 * kgp + 2 * lc2;
        float va[8], vb[8], vc[8], vd[8];
        #pragma unroll
        for (int i = 0; i < 8; ++i) { va[i]=0.f; vb[i]=0.f; vc[i]=0.f; vd[i]=0.f; }
        int ga = t0 - 63 + j0;
        #pragma unroll
        for (int rr = 0; rr < 4; ++rr) {
            int gl = ga + ((rr & 1) ? 1 : 0) + ((rr >> 1) ? 8 : 0);
            float* dstv = (rr == 0) ? va : (rr == 1) ? vb : (rr == 2) ? vc : vd;
            if (gl >= 0 && gl < S_) {
                const float4* src = reinterpret_cast<const float4*>(
                    vg + (((size_t)batch * S_ + gl) * NH_ + head) * HD_ + 8 * c);
                float4 f0 = src[0], f1 = src[1];
                dstv[0]=f0.x; dstv[1]=f0.y; dstv[2]=f0.z; dstv[3]=f0.w;
                dstv[4]=f1.x; dstv[5]=f1.y; dstv[6]=f1.z; dstv[7]=f1.w;
            }
        }
        uint2 u[8];
        #pragma unroll
        for (int i = 0; i < 8; ++i)
            u[i] = make_uint2(h2u(va[i], vb[i]), h2u(vc[i], vd[i]));
        uint4* dst = reinterpret_cast<uint4*>(pV + r * VSTR16 + 8 * c);
        #pragma unroll
        for (int i = 0; i < 4; ++i)
            dst[i] = make_uint4(u[2*i].x, u[2*i].y, u[2*i+1].x, u[2*i+1].y);
    }
    __syncthreads();

    const int qbase = wq * GQ;           // this warp's first query row
    const int kbase = qbase + kh * KPW;  // band [qbase, qbase+160) in halves

    // ---- Q fragments held in registers: 2 m-tiles x 4 k16-groups
    uint32_t qf[2][4][4];
    #pragma unroll
    for (int mt = 0; mt < 2; ++mt)
        #pragma unroll
        for (int kg = 0; kg < 4; ++kg) {
            uint2 qa = pQ[(qbase + 16*mt + lr)     * QSTR16 + kg * 4 + lc];
            uint2 qb = pQ[(qbase + 16*mt + lr + 8) * QSTR16 + kg * 4 + lc];
            qf[mt][kg][0] = qa.x; qf[mt][kg][1] = qb.x;
            qf[mt][kg][2] = qa.y; qf[mt][kg][3] = qb.y;
        }

    float Oacc[2][8][4];
    #pragma unroll
    for (int mt = 0; mt < 2; ++mt)
        #pragma unroll
        for (int nt = 0; nt < 8; ++nt)
            #pragma unroll
            for (int e = 0; e < 4; ++e) Oacc[mt][nt][e] = 0.f;
    float psum[2][2] = {{0.f, 0.f}, {0.f, 0.f}};

    // ---- streamed mainloop: 5 chunks of 16 keys
    #pragma unroll
    for (int c2 = 0; c2 < 5; ++c2) {
        // GEMM1 slice: S[32 x 16] (2 m-tiles x 2 n-tiles), B reused across mt
        float Sacc[2][2][4];
        #pragma unroll
        for (int mt = 0; mt < 2; ++mt)
            #pragma unroll
            for (int n2 = 0; n2 < 2; ++n2)
                #pragma unroll
                for (int e = 0; e < 4; ++e) Sacc[mt][n2][e] = 0.f;

        #pragma unroll
        for (int kg = 0; kg < 4; ++kg) {
            #pragma unroll
            for (int n2 = 0; n2 < 2; ++n2) {
                uint2 bv = pK[(kbase + c2*16 + n2*8 + lr) * KSTR16 + kg*4 + lc];
                mma16(Sacc[0][n2], qf[0][kg], bv.x, bv.y);
                mma16(Sacc[1][n2], qf[1][kg], bv.x, bv.y);
            }
        }

        // band mask + exp2 + row-sum partials (fp32), pack P to fp16 A-frags
        uint32_t afr2[2][4];
        #pragma unroll
        for (int mt = 0; mt < 2; ++mt) {
            #pragma unroll
            for (int h = 0; h < 2; ++h) {
                const int m = qbase + 16*mt + lr + 8*h;
                #pragma unroll
                for (int n2 = 0; n2 < 2; ++n2) {
                    const int j0 = kbase + 16*c2 + 8*n2 + 2*lc;
                    float s0 = Sacc[mt][n2][2*h + 0];
                    float s1 = Sacc[mt][n2][2*h + 1];
                    float p0 = (j0     >= m && j0     <= m + 126) ? exp2f(s0) : 0.f;
                    float p1 = (j0 + 1 >= m && j0 + 1 <= m + 126) ? exp2f(s1) : 0.f;
                    psum[mt][h] += p0 + p1;
                    Sacc[mt][n2][2*h + 0] = p0;
                    Sacc[mt][n2][2*h + 1] = p1;
                }
            }
            afr2[mt][0] = h2u(Sacc[mt][0][0], Sacc[mt][0][1]);
            afr2[mt][1] = h2u(Sacc[mt][0][2], Sacc[mt][0][3]);
            afr2[mt][2] = h2u(Sacc[mt][1][0], Sacc[mt][1][1]);
            afr2[mt][3] = h2u(Sacc[mt][1][2], Sacc[mt][1][3]);
        }

        // GEMM2 slice: O += P_chunk @ V_chunk, B reused across mt
        const int r = ((kbase >> 4) + c2) * 4 + lc;   // pV pair-row
        #pragma unroll
        for (int nt = 0; nt < 8; ++nt) {
            uint2 bv = pV[r * VSTR16 + nt * 8 + lr];
            mma16(Oacc[0][nt], afr2[0], bv.x, bv.y);
            mma16(Oacc[1][nt], afr2[1], bv.x, bv.y);
        }
    }

    // ---- row-sum partials: reduce across the 4 lanes of each quad
    #pragma unroll
    for (int mt = 0; mt < 2; ++mt)
        #pragma unroll
        for (int h = 0; h < 2; ++h) {
            float s = psum[mt][h];
            s += __shfl_xor_sync(0xffffffffu, s, 1);
            s += __shfl_xor_sync(0xffffffffu, s, 2);
            psum[mt][h] = s;
        }

    // ---- cross-half combine. Staging reuses the DEAD pQ region; all warps
    // must be past their mainloop smem reads first.
    __syncthreads();
    if (kh == 1) {
        float* so = reinterpret_cast<float*>(sm) + wq * OPG;
        #pragma unroll
        for (int mt = 0; mt < 2; ++mt)
            #pragma unroll
            for (int h = 0; h < 2; ++h) {
                const int ro = 16*mt + lr + 8*h;
                #pragma unroll
                for (int nt = 0; nt < 8; ++nt) {
                    float2 o;
                    o.x = Oacc[mt][nt][2*h + 0];
                    o.y = Oacc[mt][nt][2*h + 1];
                    *reinterpret_cast<float2*>(so + ro * OSTR + nt * 8 + 2*lc) = o;
                }
                if (lc == 0) sPS[wq * GQ + ro] = psum[mt][h];
            }
    }
    __syncthreads();

    // ---- key-half-0 warps add the staged half, normalize, store
    if (kh == 0) {
        const float* so = reinterpret_cast<const float*>(sm) + wq * OPG;
        #pragma unroll
        for (int mt = 0; mt < 2; ++mt)
            #pragma unroll
            for (int h = 0; h < 2; ++h) {
                const int ro = 16*mt + lr + 8*h;
                const int t = t0 + qbase + ro;
                if (t < S_) {
                    const float inv = 1.0f / (psum[mt][h] + sPS[wq * GQ + ro]);
                    float* dst = og + (((size_t)batch * S_ + t) * NH_ + head) * HD_;
                    #pragma unroll
                    for (int nt = 0; nt < 8; ++nt) {
                        float2 s2 = *reinterpret_cast<const float2*>(
                            so + ro * OSTR + nt * 8 + 2*lc);
                        float2 o;
                        o.x = (Oacc[mt][nt][2*h + 0] + s2.x) * inv;
                        o.y = (Oacc[mt][nt][2*h + 1] + s2.y) * inv;
                        *reinterpret_cast<float2*>(dst + nt * 8 + 2*lc) = o;
                    }
                }
            }
    }
}

extern "C" void kernel_launch(void* const* d_in, const int* in_sizes, int n_in,
                              void* d_out, int out_size)
{
    const float* q = (const float*)d_in[0];
    const float* k = (const float*)d_in[1];
    const float* v = (const float*)d_in[2];
    float* o = (float*)d_out;

    (void)cudaFuncSetAttribute(window_attn_mma,
                               cudaFuncAttributeMaxDynamicSharedMemorySize,
                               SMEM_BYTES);

    window_attn_mma<<<B_ * NH_ * NCHUNK, THREADS, SMEM_BYTES>>>(q, k, v, o);
}

// round 16
// speedup vs baseline: 2.3555x; 1.0536x over previous
#include <cuda_runtime.h>
#include <cuda_fp16.h>
#include <cstdint>
#include <cstddef>

// ---------------- problem constants ----------------
#define B_      8
#define S_      4094
#define NH_     8
#define HD_     64
#define TQ      128        // queries per CTA (4 groups of 32)
#define NKEY2   256        // key rows per CTA (128 + 126 halo, padded)
#define NCHUNK  32         // 4094 / 128 -> 32 chunks
#define GQ      32         // queries per group (2 m-tiles)
#define KPW     80         // keys per warp (2 halves cover the 158-key band)
#define THREADS 256        // 8 warps = 4 groups x 2 key halves; 2 CTAs/SM

// Q pre-scale: 1/sqrt(64) * log2(e)  (exp(s) == exp2(s'); softmax unchanged)
#define QSCALE  0.180336879f

// ---------------- packed fp16 smem layout ----------------
// pQ/pK rows: per k16-group kg, 4 uint2 (lc=0..3): {h2(k0,k0+1), h2(k0+8,k0+9)},
// k0 = 16*kg + 2*lc. Row stride 20 uint2 -> conflict-free LDS.64.
// pV pair-rows r = 4*KG + lc2: per dim d, uint2 = {h2(V[j0][d],V[j0+1][d]),
// h2(V[j0+8][d],V[j0+9][d])}, j0 = 16*KG + 2*lc2. Row stride 68 uint2.
#define QSTR16 20
#define KSTR16 20
#define VSTR16 68
#define NVROW  64          // NKEY2/16*4
#define OSTR   68          // fp32 staging stride
#define OPG    (GQ * OSTR) // 2176 floats staged per group

#define OFF_Q16 0                      // 128*20*8 = 20480 B
#define OFF_K16 20480                  // 256*20*8 = 40960 B
#define OFF_V16 61440                  // 64*68*8  = 34816 B
#define OFF_PS  96256                  // 128 floats = 512 B
#define SMEM_BYTES 96768
// O staging reuses the DEAD pQ+pK regions after the mainloop:
// group g at float offset g*OPG (4*2176*4 = 34816 B <= 61440 dead bytes).

// ---------------- helpers ----------------
__device__ __forceinline__ uint32_t h2u(float lo, float hi) {
    uint32_t u;  // first source -> upper half
    asm("cvt.rn.f16x2.f32 %0, %1, %2;" : "=r"(u) : "f"(hi), "f"(lo));
    return u;
}

// m16n8k16 fp16 mma, fp32 accumulate (family-portable, sm_80+)
__device__ __forceinline__ void mma16(float* d, const uint32_t* a,
                                      uint32_t b0, uint32_t b1) {
    asm volatile(
        "mma.sync.aligned.m16n8k16.row.col.f32.f16.f16.f32 "
        "{%0,%1,%2,%3}, {%4,%5,%6,%7}, {%8,%9}, {%0,%1,%2,%3};"
        : "+f"(d[0]), "+f"(d[1]), "+f"(d[2]), "+f"(d[3])
        : "r"(a[0]), "r"(a[1]), "r"(a[2]), "r"(a[3]), "r"(b0), "r"(b1));
}

// ---------------- kernel ----------------
__global__ __launch_bounds__(THREADS, 2)
void window_attn_mma(const float* __restrict__ qg, const float* __restrict__ kg,
                     const float* __restrict__ vg, float* __restrict__ og)
{
    extern __shared__ char sm[];
    uint2* pQ  = reinterpret_cast<uint2*>(sm + OFF_Q16);
    uint2* pK  = reinterpret_cast<uint2*>(sm + OFF_K16);
    uint2* pV  = reinterpret_cast<uint2*>(sm + OFF_V16);
    float* sPS = reinterpret_cast<float*>(sm + OFF_PS);

    const int bx    = blockIdx.x;
    const int chunk = bx & (NCHUNK - 1);
    const int head  = (bx >> 5) & (NH_ - 1);
    const int batch = bx >> 8;
    const int t0    = chunk * TQ;

    const int tid  = threadIdx.x;
    const int w    = tid >> 5;
    const int lane = tid & 31;
    const int lr   = lane >> 2;   // row-in-fragment
    const int lc   = lane & 3;    // col-in-fragment
    const int wq   = w & 3;       // query group (32 rows)
    const int kh   = w >> 2;      // key half of the band (80 keys; 0,1)

    // ---- fill packed fp16 Q (scaled by 1/8*log2e). One (row, k16-group)/item.
    for (int idx = tid; idx < TQ * 4; idx += THREADS) {
        int m = idx >> 2, g = idx & 3;
        int t = t0 + m;
        float v[16];
        #pragma unroll
        for (int i = 0; i < 16; ++i) v[i] = 0.f;
        if (t < S_) {
            const float4* src = reinterpret_cast<const float4*>(
                qg + (((size_t)batch * S_ + t) * NH_ + head) * HD_ + 16 * g);
            #pragma unroll
            for (int i = 0; i < 4; ++i) {
                float4 f = src[i];
                v[4*i+0] = f.x * QSCALE; v[4*i+1] = f.y * QSCALE;
                v[4*i+2] = f.z * QSCALE; v[4*i+3] = f.w * QSCALE;
            }
        }
        uint2 u[4];
        #pragma unroll
        for (int c = 0; c < 4; ++c)
            u[c] = make_uint2(h2u(v[2*c], v[2*c+1]), h2u(v[2*c+8], v[2*c+9]));
        uint4* dst = reinterpret_cast<uint4*>(pQ + m * QSTR16 + g * 4);
        dst[0] = make_uint4(u[0].x, u[0].y, u[1].x, u[1].y);
        dst[1] = make_uint4(u[2].x, u[2].y, u[3].x, u[3].y);
    }
    // ---- fill packed fp16 K; out-of-sequence rows ZERO (reference padding)
    for (int idx = tid; idx < NKEY2 * 4; idx += THREADS) {
        int r = idx >> 2, g = idx & 3;
        int gl = t0 - 63 + r;
        float v[16];
        #pragma unroll
        for (int i = 0; i < 16; ++i) v[i] = 0.f;
        if (gl >= 0 && gl < S_) {
            const float4* src = reinterpret_cast<const float4*>(
                kg + (((size_t)batch * S_ + gl) * NH_ + head) * HD_ + 16 * g);
            #pragma unroll
            for (int i = 0; i < 4; ++i) {
                float4 f = src[i];
                v[4*i+0] = f.x; v[4*i+1] = f.y; v[4*i+2] = f.z; v[4*i+3] = f.w;
            }
        }
        uint2 u[4];
        #pragma unroll
        for (int c = 0; c < 4; ++c)
            u[c] = make_uint2(h2u(v[2*c], v[2*c+1]), h2u(v[2*c+8], v[2*c+9]));
        uint4* dst = reinterpret_cast<uint4*>(pK + r * KSTR16 + g * 4);
        dst[0] = make_uint4(u[0].x, u[0].y, u[1].x, u[1].y);
        dst[1] = make_uint4(u[2].x, u[2].y, u[3].x, u[3].y);
    }
    // ---- fill packed fp16 V: item = (pair-row r, 8-dim chunk c)
    for (int idx = tid; idx < NVROW * 8; idx += THREADS) {
        int r = idx >> 3, c = idx & 7;
        int kgp = r >> 2, lc2 = r & 3;
        int j0 = 16 * kgp + 2 * lc2;
        float va[8], vb[8], vc[8], vd[8];
        #pragma unroll
        for (int i = 0; i < 8; ++i) { va[i]=0.f; vb[i]=0.f; vc[i]=0.f; vd[i]=0.f; }
        int ga = t0 - 63 + j0;
        #pragma unroll
        for (int rr = 0; rr < 4; ++rr) {
            int gl = ga + ((rr & 1) ? 1 : 0) + ((rr >> 1) ? 8 : 0);
            float* dstv = (rr == 0) ? va : (rr == 1) ? vb : (rr == 2) ? vc : vd;
            if (gl >= 0 && gl < S_) {
                const float4* src = reinterpret_cast<const float4*>(
                    vg + (((size_t)batch * S_ + gl) * NH_ + head) * HD_ + 8 * c);
                float4 f0 = src[0], f1 = src[1];
                dstv[0]=f0.x; dstv[1]=f0.y; dstv[2]=f0.z; dstv[3]=f0.w;
                dstv[4]=f1.x; dstv[5]=f1.y; dstv[6]=f1.z; dstv[7]=f1.w;
            }
        }
        uint2 u[8];
        #pragma unroll
        for (int i = 0; i < 8; ++i)
            u[i] = make_uint2(h2u(va[i], vb[i]), h2u(vc[i], vd[i]));
        uint4* dst = reinterpret_cast<uint4*>(pV + r * VSTR16 + 8 * c);
        #pragma unroll
        for (int i = 0; i < 4; ++i)
            dst[i] = make_uint4(u[2*i].x, u[2*i].y, u[2*i+1].x, u[2*i+1].y);
    }
    __syncthreads();

    const int qbase = wq * GQ;           // this warp's first query row
    const int kbase = qbase + kh * KPW;  // band [qbase, qbase+160) in halves

    // ---- Q fragments held in registers: 2 m-tiles x 4 k16-groups
    uint32_t qf[2][4][4];
    #pragma unroll
    for (int mt = 0; mt < 2; ++mt)
        #pragma unroll
        for (int kg = 0; kg < 4; ++kg) {
            uint2 qa = pQ[(qbase + 16*mt + lr)     * QSTR16 + kg * 4 + lc];
            uint2 qb = pQ[(qbase + 16*mt + lr + 8) * QSTR16 + kg * 4 + lc];
            qf[mt][kg][0] = qa.x; qf[mt][kg][1] = qb.x;
            qf[mt][kg][2] = qa.y; qf[mt][kg][3] = qb.y;
        }

    float Oacc[2][8][4];
    #pragma unroll
    for (int mt = 0; mt < 2; ++mt)
        #pragma unroll
        for (int nt = 0; nt < 8; ++nt)
            #pragma unroll
            for (int e = 0; e < 4; ++e) Oacc[mt][nt][e] = 0.f;
    float psum[2][2] = {{0.f, 0.f}, {0.f, 0.f}};

    // ---- streamed mainloop: 5 chunks of 16 keys
    #pragma unroll
    for (int c2 = 0; c2 < 5; ++c2) {
        // GEMM1 slice: S[32 x 16] (2 m-tiles x 2 n-tiles), B reused across mt
        float Sacc[2][2][4];
        #pragma unroll
        for (int mt = 0; mt < 2; ++mt)
            #pragma unroll
            for (int n2 = 0; n2 < 2; ++n2)
                #pragma unroll
                for (int e = 0; e < 4; ++e) Sacc[mt][n2][e] = 0.f;

        #pragma unroll
        for (int kg = 0; kg < 4; ++kg) {
            #pragma unroll
            for (int n2 = 0; n2 < 2; ++n2) {
                uint2 bv = pK[(kbase + c2*16 + n2*8 + lr) * KSTR16 + kg*4 + lc];
                mma16(Sacc[0][n2], qf[0][kg], bv.x, bv.y);
                mma16(Sacc[1][n2], qf[1][kg], bv.x, bv.y);
            }
        }

        // band mask (single unsigned range compare) + exp2 + row-sum partials,
        // pack P to fp16 A-fragments
        uint32_t afr2[2][4];
        #pragma unroll
        for (int mt = 0; mt < 2; ++mt) {
            #pragma unroll
            for (int h = 0; h < 2; ++h) {
                const int m = qbase + 16*mt + lr + 8*h;
                #pragma unroll
                for (int n2 = 0; n2 < 2; ++n2) {
                    const int j0 = kbase + 16*c2 + 8*n2 + 2*lc;
                    float s0 = Sacc[mt][n2][2*h + 0];
                    float s1 = Sacc[mt][n2][2*h + 1];
                    float p0 = ((unsigned)(j0     - m) <= 126u) ? exp2f(s0) : 0.f;
                    float p1 = ((unsigned)(j0 + 1 - m) <= 126u) ? exp2f(s1) : 0.f;
                    psum[mt][h] += p0 + p1;
                    Sacc[mt][n2][2*h + 0] = p0;
                    Sacc[mt][n2][2*h + 1] = p1;
                }
            }
            afr2[mt][0] = h2u(Sacc[mt][0][0], Sacc[mt][0][1]);
            afr2[mt][1] = h2u(Sacc[mt][0][2], Sacc[mt][0][3]);
            afr2[mt][2] = h2u(Sacc[mt][1][0], Sacc[mt][1][1]);
            afr2[mt][3] = h2u(Sacc[mt][1][2], Sacc[mt][1][3]);
        }

        // GEMM2 slice: O += P_chunk @ V_chunk, B reused across mt
        const int r = ((kbase >> 4) + c2) * 4 + lc;   // pV pair-row
        #pragma unroll
        for (int nt = 0; nt < 8; ++nt) {
            uint2 bv = pV[r * VSTR16 + nt * 8 + lr];
            mma16(Oacc[0][nt], afr2[0], bv.x, bv.y);
            mma16(Oacc[1][nt], afr2[1], bv.x, bv.y);
        }
    }

    // ---- row-sum partials: reduce across the 4 lanes of each quad
    #pragma unroll
    for (int mt = 0; mt < 2; ++mt)
        #pragma unroll
        for (int h = 0; h < 2; ++h) {
            float s = psum[mt][h];
            s += __shfl_xor_sync(0xffffffffu, s, 1);
            s += __shfl_xor_sync(0xffffffffu, s, 2);
            psum[mt][h] = s;
        }

    // ---- cross-half combine. Staging reuses the DEAD pQ/pK regions; all
    // warps must be past their mainloop smem reads first.
    __syncthreads();
    if (kh == 1) {
        float* so = reinterpret_cast<float*>(sm) + wq * OPG;
        #pragma unroll
        for (int mt = 0; mt < 2; ++mt)
            #pragma unroll
            for (int h = 0; h < 2; ++h) {
                const int ro = 16*mt + lr + 8*h;
                #pragma unroll
                for (int nt = 0; nt < 8; ++nt) {
                    float2 o;
                    o.x = Oacc[mt][nt][2*h + 0];
                    o.y = Oacc[mt][nt][2*h + 1];
                    *reinterpret_cast<float2*>(so + ro * OSTR + nt * 8 + 2*lc) = o;
                }
                if (lc == 0) sPS[wq * GQ + ro] = psum[mt][h];
            }
    }
    __syncthreads();

    // ---- key-half-0 warps add the staged half, normalize, store
    if (kh == 0) {
        const float* so = reinterpret_cast<const float*>(sm) + wq * OPG;
        #pragma unroll
        for (int mt = 0; mt < 2; ++mt)
            #pragma unroll
            for (int h = 0; h < 2; ++h) {
                const int ro = 16*mt + lr + 8*h;
                const int t = t0 + qbase + ro;
                if (t < S_) {
                    const float inv = 1.0f / (psum[mt][h] + sPS[wq * GQ + ro]);
                    float* dst = og + (((size_t)batch * S_ + t) * NH_ + head) * HD_;
                    #pragma unroll
                    for (int nt = 0; nt < 8; ++nt) {
                        float2 s2 = *reinterpret_cast<const float2*>(
                            so + ro * OSTR + nt * 8 + 2*lc);
                        float2 o;
                        o.x = (Oacc[mt][nt][2*h + 0] + s2.x) * inv;
                        o.y = (Oacc[mt][nt][2*h + 1] + s2.y) * inv;
                        *reinterpret_cast<float2*>(dst + nt * 8 + 2*lc) = o;
                    }
                }
            }
    }
}

extern "C" void kernel_launch(void* const* d_in, const int* in_sizes, int n_in,
                              void* d_out, int out_size)
{
    const float* q = (const float*)d_in[0];
    const float* k = (const float*)d_in[1];
    const float* v = (const float*)d_in[2];
    float* o = (float*)d_out;

    (void)cudaFuncSetAttribute(window_attn_mma,
                               cudaFuncAttributeMaxDynamicSharedMemorySize,
                               SMEM_BYTES);

    window_attn_mma<<<B_ * NH_ * NCHUNK, THREADS, SMEM_BYTES>>>(q, k, v, o);
}

// round 17
// speedup vs baseline: 2.4966x; 1.0599x over previous
#include <cuda_runtime.h>
#include <cuda_fp16.h>
#include <cstdint>
#include <cstddef>

// ---------------- problem constants ----------------
#define B_      8
#define S_      4094
#define NH_     8
#define HD_     64
#define TQ      128        // queries per CTA (4 groups of 32)
#define NKEY2   256        // key rows per CTA (128 + 126 halo, padded)
#define NCHUNK  32         // 4094 / 128 -> 32 chunks
#define GQ      32         // queries per group (2 m-tiles)
#define KPW     80         // keys per warp (2 halves cover the 158-key band)
#define THREADS 256        // 8 warps = 4 groups x 2 key halves; 2 CTAs/SM

// Q pre-scale: 1/sqrt(64) * log2(e)  (exp(s) == exp2(s'); softmax unchanged)
#define QSCALE  0.180336879f

// ---------------- smem layout ----------------
// Q/K: canonical row-major fp16, 64 halfs + 8 pad = 72 halfs = 144 B/row.
//      144 B stride => ldmatrix row-starts hit banks {4i..4i+3}, conflict-free.
// pV pair-rows r = 4*KG + lc2: per dim d, uint2 = {h2(V[j0][d],V[j0+1][d]),
//      h2(V[j0+8][d],V[j0+9][d])}, j0 = 16*KG + 2*lc2. Row stride 68 uint2.
#define QKROWB 144         // bytes per Q/K row
#define VSTR16 68
#define NVROW  64          // NKEY2/16*4
#define OSTR   68          // fp32 staging stride
#define OPG    (GQ * OSTR) // 2176 floats staged per group

#define OFF_Q16 0                      // 128*144 = 18432 B
#define OFF_K16 18432                  // 256*144 = 36864 B
#define OFF_V16 55296                  // 64*68*8 = 34816 B
#define OFF_PS  90112                  // 128 floats = 512 B
#define SMEM_BYTES 90624
// O staging reuses the DEAD Q+K regions after the mainloop:
// group g at float offset g*OPG (4*2176*4 = 34816 B <= 55296 dead bytes).

// ---------------- helpers ----------------
__device__ __forceinline__ uint32_t h2u(float lo, float hi) {
    uint32_t u;  // first source -> upper half
    asm("cvt.rn.f16x2.f32 %0, %1, %2;" : "=r"(u) : "f"(hi), "f"(lo));
    return u;
}

// ldmatrix x4: four 8x8 fp16 matrices, one address per lane
__device__ __forceinline__ void ldm4(uint32_t* r, uint32_t addr) {
    asm volatile("ldmatrix.sync.aligned.m8n8.x4.shared.b16 {%0,%1,%2,%3}, [%4];"
                 : "=r"(r[0]), "=r"(r[1]), "=r"(r[2]), "=r"(r[3]) : "r"(addr));
}

// m16n8k16 fp16 mma, fp32 accumulate (family-portable, sm_80+)
__device__ __forceinline__ void mma16(float* d, const uint32_t* a,
                                      uint32_t b0, uint32_t b1) {
    asm volatile(
        "mma.sync.aligned.m16n8k16.row.col.f32.f16.f16.f32 "
        "{%0,%1,%2,%3}, {%4,%5,%6,%7}, {%8,%9}, {%0,%1,%2,%3};"
        : "+f"(d[0]), "+f"(d[1]), "+f"(d[2]), "+f"(d[3])
        : "r"(a[0]), "r"(a[1]), "r"(a[2]), "r"(a[3]), "r"(b0), "r"(b1));
}

// ---------------- kernel ----------------
__global__ __launch_bounds__(THREADS, 2)
void window_attn_mma(const float* __restrict__ qg, const float* __restrict__ kg,
                     const float* __restrict__ vg, float* __restrict__ og)
{
    extern __shared__ char sm[];
    uint2* pV  = reinterpret_cast<uint2*>(sm + OFF_V16);
    float* sPS = reinterpret_cast<float*>(sm + OFF_PS);

    const int bx    = blockIdx.x;
    const int chunk = bx & (NCHUNK - 1);
    const int head  = (bx >> 5) & (NH_ - 1);
    const int batch = bx >> 8;
    const int t0    = chunk * TQ;

    const int tid  = threadIdx.x;
    const int w    = tid >> 5;
    const int lane = tid & 31;
    const int lr   = lane >> 2;   // row-in-fragment
    const int lc   = lane & 3;    // col-in-fragment
    const int wq   = w & 3;       // query group (32 rows)
    const int kh   = w >> 2;      // key half of the band (80 keys; 0,1)

    // ---- fill canonical fp16 Q (scaled). Item = (row, 16-half group g).
    for (int idx = tid; idx < TQ * 4; idx += THREADS) {
        int m = idx >> 2, g = idx & 3;
        int t = t0 + m;
        float v[16];
        #pragma unroll
        for (int i = 0; i < 16; ++i) v[i] = 0.f;
        if (t < S_) {
            const float4* src = reinterpret_cast<const float4*>(
                qg + (((size_t)batch * S_ + t) * NH_ + head) * HD_ + 16 * g);
            #pragma unroll
            for (int i = 0; i < 4; ++i) {
                float4 f = src[i];
                v[4*i+0] = f.x * QSCALE; v[4*i+1] = f.y * QSCALE;
                v[4*i+2] = f.z * QSCALE; v[4*i+3] = f.w * QSCALE;
            }
        }
        uint32_t u[8];
        #pragma unroll
        for (int i = 0; i < 8; ++i) u[i] = h2u(v[2*i], v[2*i+1]);
        uint4* dst = reinterpret_cast<uint4*>(sm + OFF_Q16 + m * QKROWB + g * 32);
        dst[0] = make_uint4(u[0], u[1], u[2], u[3]);
        dst[1] = make_uint4(u[4], u[5], u[6], u[7]);
    }
    // ---- fill canonical fp16 K; out-of-sequence rows ZERO (reference padding)
    for (int idx = tid; idx < NKEY2 * 4; idx += THREADS) {
        int r = idx >> 2, g = idx & 3;
        int gl = t0 - 63 + r;
        float v[16];
        #pragma unroll
        for (int i = 0; i < 16; ++i) v[i] = 0.f;
        if (gl >= 0 && gl < S_) {
            const float4* src = reinterpret_cast<const float4*>(
                kg + (((size_t)batch * S_ + gl) * NH_ + head) * HD_ + 16 * g);
            #pragma unroll
            for (int i = 0; i < 4; ++i) {
                float4 f = src[i];
                v[4*i+0] = f.x; v[4*i+1] = f.y; v[4*i+2] = f.z; v[4*i+3] = f.w;
            }
        }
        uint32_t u[8];
        #pragma unroll
        for (int i = 0; i < 8; ++i) u[i] = h2u(v[2*i], v[2*i+1]);
        uint4* dst = reinterpret_cast<uint4*>(sm + OFF_K16 + r * QKROWB + g * 32);
        dst[0] = make_uint4(u[0], u[1], u[2], u[3]);
        dst[1] = make_uint4(u[4], u[5], u[6], u[7]);
    }
    // ---- fill packed fp16 V: item = (pair-row r, 8-dim chunk c)
    for (int idx = tid; idx < NVROW * 8; idx += THREADS) {
        int r = idx >> 3, c = idx & 7;
        int kgp = r >> 2, lc2 = r & 3;
        int j0 = 16 * kgp + 2 * lc2;
        float va[8], vb[8], vc[8], vd[8];
        #pragma unroll
        for (int i = 0; i < 8; ++i) { va[i]=0.f; vb[i]=0.f; vc[i]=0.f; vd[i]=0.f; }
        int ga = t0 - 63 + j0;
        #pragma unroll
        for (int rr = 0; rr < 4; ++rr) {
            int gl = ga + ((rr & 1) ? 1 : 0) + ((rr >> 1) ? 8 : 0);
            float* dstv = (rr == 0) ? va : (rr == 1) ? vb : (rr == 2) ? vc : vd;
            if (gl >= 0 && gl < S_) {
                const float4* src = reinterpret_cast<const float4*>(
                    vg + (((size_t)batch * S_ + gl) * NH_ + head) * HD_ + 8 * c);
                float4 f0 = src[0], f1 = src[1];
                dstv[0]=f0.x; dstv[1]=f0.y; dstv[2]=f0.z; dstv[3]=f0.w;
                dstv[4]=f1.x; dstv[5]=f1.y; dstv[6]=f1.z; dstv[7]=f1.w;
            }
        }
        uint2 u[8];
        #pragma unroll
        for (int i = 0; i < 8; ++i)
            u[i] = make_uint2(h2u(va[i], vb[i]), h2u(vc[i], vd[i]));
        uint4* dst = reinterpret_cast<uint4*>(pV + r * VSTR16 + 8 * c);
        #pragma unroll
        for (int i = 0; i < 4; ++i)
            dst[i] = make_uint4(u[2*i].x, u[2*i].y, u[2*i+1].x, u[2*i+1].y);
    }
    __syncthreads();

    const int qbase = wq * GQ;           // this warp's first query row
    const int kbase = qbase + kh * KPW;  // band [qbase, qbase+160) in halves

    // ---- ldmatrix lane address components
    const uint32_t smem32 = (uint32_t)__cvta_generic_to_shared(sm);
    // A-operand (Q): lanes 0-15 -> rows 0-15 (k+0); lanes 16-31 -> rows 0-15 (k+8)
    const uint32_t qa_lane = (uint32_t)((lane & 15) * QKROWB + (lane >> 4) * 16);
    // B-operand (K): lanes 0-7 keys+0..7 k+0; 8-15 keys+0..7 k+8;
    //                16-23 keys+8..15 k+0; 24-31 keys+8..15 k+8
    const uint32_t ka_lane = (uint32_t)(((lane & 7) + ((lane >> 4) << 3)) * QKROWB
                                        + (((lane >> 3) & 1) * 16));

    // ---- Q fragments held in registers: 2 m-tiles x 4 k16-groups (8 ldmatrix)
    uint32_t qf[2][4][4];
    #pragma unroll
    for (int mt = 0; mt < 2; ++mt) {
        uint32_t qaddr = smem32 + OFF_Q16 + (qbase + 16*mt) * QKROWB + qa_lane;
        #pragma unroll
        for (int kg = 0; kg < 4; ++kg)
            ldm4(qf[mt][kg], qaddr + kg * 32);
    }

    float Oacc[2][8][4];
    #pragma unroll
    for (int mt = 0; mt < 2; ++mt)
        #pragma unroll
        for (int nt = 0; nt < 8; ++nt)
            #pragma unroll
            for (int e = 0; e < 4; ++e) Oacc[mt][nt][e] = 0.f;
    float psum[2][2] = {{0.f, 0.f}, {0.f, 0.f}};

    const uint32_t kaddr0 = smem32 + OFF_K16 + kbase * QKROWB + ka_lane;

    // ---- streamed mainloop: 5 chunks of 16 keys
    #pragma unroll
    for (int c2 = 0; c2 < 5; ++c2) {
        // GEMM1 slice: S[32 x 16]; one ldmatrix.x4 per kg feeds 4 MMAs
        float Sacc[2][2][4];
        #pragma unroll
        for (int mt = 0; mt < 2; ++mt)
            #pragma unroll
            for (int n2 = 0; n2 < 2; ++n2)
                #pragma unroll
                for (int e = 0; e < 4; ++e) Sacc[mt][n2][e] = 0.f;

        #pragma unroll
        for (int kg = 0; kg < 4; ++kg) {
            uint32_t bq[4];   // {b0_nt0, b1_nt0, b0_nt1, b1_nt1}
            ldm4(bq, kaddr0 + c2 * 16 * QKROWB + kg * 32);
            mma16(Sacc[0][0], qf[0][kg], bq[0], bq[1]);
            mma16(Sacc[1][0], qf[1][kg], bq[0], bq[1]);
            mma16(Sacc[0][1], qf[0][kg], bq[2], bq[3]);
            mma16(Sacc[1][1], qf[1][kg], bq[2], bq[3]);
        }

        // band mask (single unsigned range compare) + exp2 + row-sum partials,
        // pack P to fp16 A-fragments
        uint32_t afr2[2][4];
        #pragma unroll
        for (int mt = 0; mt < 2; ++mt) {
            #pragma unroll
            for (int h = 0; h < 2; ++h) {
                const int m = qbase + 16*mt + lr + 8*h;
                #pragma unroll
                for (int n2 = 0; n2 < 2; ++n2) {
                    const int j0 = kbase + 16*c2 + 8*n2 + 2*lc;
                    float s0 = Sacc[mt][n2][2*h + 0];
                    float s1 = Sacc[mt][n2][2*h + 1];
                    float p0 = ((unsigned)(j0     - m) <= 126u) ? exp2f(s0) : 0.f;
                    float p1 = ((unsigned)(j0 + 1 - m) <= 126u) ? exp2f(s1) : 0.f;
                    psum[mt][h] += p0 + p1;
                    Sacc[mt][n2][2*h + 0] = p0;
                    Sacc[mt][n2][2*h + 1] = p1;
                }
            }
            afr2[mt][0] = h2u(Sacc[mt][0][0], Sacc[mt][0][1]);
            afr2[mt][1] = h2u(Sacc[mt][0][2], Sacc[mt][0][3]);
            afr2[mt][2] = h2u(Sacc[mt][1][0], Sacc[mt][1][1]);
            afr2[mt][3] = h2u(Sacc[mt][1][2], Sacc[mt][1][3]);
        }

        // GEMM2 slice: O += P_chunk @ V_chunk, B reused across mt
        const int r = ((kbase >> 4) + c2) * 4 + lc;   // pV pair-row
        #pragma unroll
        for (int nt = 0; nt < 8; ++nt) {
            uint2 bv = pV[r * VSTR16 + nt * 8 + lr];
            mma16(Oacc[0][nt], afr2[0], bv.x, bv.y);
            mma16(Oacc[1][nt], afr2[1], bv.x, bv.y);
        }
    }

    // ---- row-sum partials: reduce across the 4 lanes of each quad
    #pragma unroll
    for (int mt = 0; mt < 2; ++mt)
        #pragma unroll
        for (int h = 0; h < 2; ++h) {
            float s = psum[mt][h];
            s += __shfl_xor_sync(0xffffffffu, s, 1);
            s += __shfl_xor_sync(0xffffffffu, s, 2);
            psum[mt][h] = s;
        }

    // ---- cross-half combine. Staging reuses the DEAD Q/K regions; all
    // warps must be past their mainloop smem reads first.
    __syncthreads();
    if (kh == 1) {
        float* so = reinterpret_cast<float*>(sm) + wq * OPG;
        #pragma unroll
        for (int mt = 0; mt < 2; ++mt)
            #pragma unroll
            for (int h = 0; h < 2; ++h) {
                const int ro = 16*mt + lr + 8*h;
                #pragma unroll
                for (int nt = 0; nt < 8; ++nt) {
                    float2 o;
                    o.x = Oacc[mt][nt][2*h + 0];
                    o.y = Oacc[mt][nt][2*h + 1];
                    *reinterpret_cast<float2*>(so + ro * OSTR + nt * 8 + 2*lc) = o;
                }
                if (lc == 0) sPS[wq * GQ + ro] = psum[mt][h];
            }
    }
    __syncthreads();

    // ---- key-half-0 warps add the staged half, normalize, store
    if (kh == 0) {
        const float* so = reinterpret_cast<const float*>(sm) + wq * OPG;
        #pragma unroll
        for (int mt = 0; mt < 2; ++mt)
            #pragma unroll
            for (int h = 0; h < 2; ++h) {
                const int ro = 16*mt + lr + 8*h;
                const int t = t0 + qbase + ro;
                if (t < S_) {
                    const float inv = 1.0f / (psum[mt][h] + sPS[wq * GQ + ro]);
                    float* dst = og + (((size_t)batch * S_ + t) * NH_ + head) * HD_;
                    #pragma unroll
                    for (int nt = 0; nt < 8; ++nt) {
                        float2 s2 = *reinterpret_cast<const float2*>(
                            so + ro * OSTR + nt * 8 + 2*lc);
                        float2 o;
                        o.x = (Oacc[mt][nt][2*h + 0] + s2.x) * inv;
                        o.y = (Oacc[mt][nt][2*h + 1] + s2.y) * inv;
                        *reinterpret_cast<float2*>(dst + nt * 8 + 2*lc) = o;
                    }
                }
            }
    }
}

extern "C" void kernel_launch(void* const* d_in, const int* in_sizes, int n_in,
                              void* d_out, int out_size)
{
    const float* q = (const float*)d_in[0];
    const float* k = (const float*)d_in[1];
    const float* v = (const float*)d_in[2];
    float* o = (float*)d_out;

    (void)cudaFuncSetAttribute(window_attn_mma,
                               cudaFuncAttributeMaxDynamicSharedMemorySize,
                               SMEM_BYTES);

    window_attn_mma<<<B_ * NH_ * NCHUNK, THREADS, SMEM_BYTES>>>(q, k, v, o);
}